// round 2
// baseline (speedup 1.0000x reference)
#include <cuda_runtime.h>

// ---------------- problem constants ----------------
#define CHN   16
#define EMB   128
#define KF    48            // 3*CHN input features
#define HGT   256
#define WID   256
#define BATCH 16
#define TPX   64            // pixels per tile (contiguous along W)
#define TILES_PER_ROW (WID / TPX)            // 4
#define TILES_PER_IMG (HGT * TILES_PER_ROW)  // 1024
#define NT    (BATCH * TILES_PER_IMG)        // 16384
#define NTHREADS 256

// ---------------- shared memory layout (float offsets) ----------------
#define SWS 132                 // padded stride for W1/W2 and activation buffers
#define SW3 20                  // padded stride for W3
#define OFF_W1   0
#define OFF_W2   (OFF_W1 + KF  * SWS)     // 6336
#define OFF_W3   (OFF_W2 + EMB * SWS)     // +16896
#define OFF_B1   (OFF_W3 + EMB * SW3)     // +2560
#define OFF_B2   (OFF_B1 + EMB)
#define OFF_B3   (OFF_B2 + EMB)
#define OFF_BUF0 (OFF_B3 + 16)
#define OFF_BUF1 (OFF_BUF0 + TPX * SWS)
#define XS_ROW   66                        // TPX + 2 halo
#define OFF_XS   (OFF_BUF1 + TPX * SWS)
#define OFF_SEL  (OFF_XS + CHN * 3 * XS_ROW)
#define SMEM_FLOATS (OFF_SEL + TPX)
#define SMEM_BYTES  (SMEM_FLOATS * 4)      // ~184.8 KB

// ---------------- helpers ----------------
__device__ __forceinline__ unsigned f2tf(float f) {
    unsigned r;
    asm("cvt.rna.tf32.f32 %0, %1;" : "=r"(r) : "f"(f));
    return r;
}

__device__ __forceinline__ void mma_tf32(float* d,
                                         unsigned a0, unsigned a1, unsigned a2, unsigned a3,
                                         unsigned b0, unsigned b1) {
    asm volatile(
        "mma.sync.aligned.m16n8k8.row.col.f32.tf32.tf32.f32 "
        "{%0,%1,%2,%3}, {%4,%5,%6,%7}, {%8,%9}, {%0,%1,%2,%3};\n"
        : "+f"(d[0]), "+f"(d[1]), "+f"(d[2]), "+f"(d[3])
        : "r"(a0), "r"(a1), "r"(a2), "r"(a3), "r"(b0), "r"(b1));
}

// One fused GEMM+bias+relu layer: Out[64 x 128] = relu(A[64 x (8*KT)] @ Bw + bias)
// A, Out: stride SWS in smem (tf32 bits). Bw: [8*KT x 128] stride SWS (tf32 bits).
template <int KT>
__device__ __forceinline__ void gemm_layer(const unsigned* __restrict__ A,
                                           const unsigned* __restrict__ Bw,
                                           const float* __restrict__ bias,
                                           unsigned* __restrict__ Out,
                                           int rowBase, int colBase, int g, int tq) {
    float acc[8][4];
#pragma unroll
    for (int n = 0; n < 8; n++)
#pragma unroll
        for (int j = 0; j < 4; j++) acc[n][j] = 0.f;

#pragma unroll
    for (int kt = 0; kt < KT; kt++) {
        const int k0 = kt * 8;
        unsigned a0 = A[(rowBase + g)     * SWS + k0 + tq];
        unsigned a1 = A[(rowBase + g + 8) * SWS + k0 + tq];
        unsigned a2 = A[(rowBase + g)     * SWS + k0 + tq + 4];
        unsigned a3 = A[(rowBase + g + 8) * SWS + k0 + tq + 4];
#pragma unroll
        for (int nt = 0; nt < 8; nt++) {
            const int n0 = colBase + nt * 8;
            unsigned b0 = Bw[(k0 + tq)     * SWS + n0 + g];
            unsigned b1 = Bw[(k0 + tq + 4) * SWS + n0 + g];
            mma_tf32(acc[nt], a0, a1, a2, a3, b0, b1);
        }
    }
    // epilogue: bias + relu + tf32 store
#pragma unroll
    for (int nt = 0; nt < 8; nt++) {
        const int n0 = colBase + nt * 8;
        const int c0 = n0 + 2 * tq;
        float bb0 = bias[c0], bb1 = bias[c0 + 1];
        float v0 = fmaxf(acc[nt][0] + bb0, 0.f);
        float v1 = fmaxf(acc[nt][1] + bb1, 0.f);
        float v2 = fmaxf(acc[nt][2] + bb0, 0.f);
        float v3 = fmaxf(acc[nt][3] + bb1, 0.f);
        Out[(rowBase + g)     * SWS + c0]     = f2tf(v0);
        Out[(rowBase + g)     * SWS + c0 + 1] = f2tf(v1);
        Out[(rowBase + g + 8) * SWS + c0]     = f2tf(v2);
        Out[(rowBase + g + 8) * SWS + c0 + 1] = f2tf(v3);
    }
}

// ---------------- kernel ----------------
__global__ void __launch_bounds__(NTHREADS, 1)
nca_kernel(const float* __restrict__ x,  const float* __restrict__ fm,
           const float* __restrict__ w1, const float* __restrict__ b1,
           const float* __restrict__ w2, const float* __restrict__ b2,
           const float* __restrict__ w3, const float* __restrict__ b3,
           float* __restrict__ out) {
    extern __shared__ float sm[];
    unsigned* smu = reinterpret_cast<unsigned*>(sm);

    const int tid  = threadIdx.x;
    const int lane = tid & 31;
    const int wid  = tid >> 5;
    const int g    = lane >> 2;      // groupID (0..7)
    const int tq   = lane & 3;       // threadID_in_group (0..3)
    const int warpM = wid & 3;       // 4 warps over M (rows of 16)
    const int warpN = wid >> 2;      // 2 warps over N (cols of 64)
    const int rowBase = warpM * 16;
    const int colBase = warpN * 64;

    // ---- load + convert weights to tf32 in smem (once per CTA) ----
    for (int i = tid; i < KF * EMB; i += NTHREADS)
        smu[OFF_W1 + (i >> 7) * SWS + (i & 127)] = f2tf(w1[i]);
    for (int i = tid; i < EMB * EMB; i += NTHREADS)
        smu[OFF_W2 + (i >> 7) * SWS + (i & 127)] = f2tf(w2[i]);
    for (int i = tid; i < EMB * CHN; i += NTHREADS)
        smu[OFF_W3 + (i >> 4) * SW3 + (i & 15)] = f2tf(w3[i]);
    for (int i = tid; i < EMB; i += NTHREADS) {
        sm[OFF_B1 + i] = b1[i];
        sm[OFF_B2 + i] = b2[i];
    }
    if (tid < CHN) sm[OFF_B3 + tid] = b3[tid];
    __syncthreads();

    for (int t = blockIdx.x; t < NT; t += gridDim.x) {
        const int b   = t >> 10;           // TILES_PER_IMG = 1024
        const int rem = t & 1023;
        const int y   = rem >> 2;          // TILES_PER_ROW = 4
        const int w0  = (rem & 3) << 6;

        // ---- stage x halo: 16ch x 3rows x 66cols, zero-padded ----
        for (int i = tid; i < CHN * 3 * XS_ROW; i += NTHREADS) {
            const int c   = i / (3 * XS_ROW);
            const int r2  = i - c * 3 * XS_ROW;
            const int dy  = r2 / XS_ROW;
            const int col = r2 - dy * XS_ROW;
            const int yy = y + dy - 1;
            const int xx = w0 + col - 1;
            float v = 0.f;
            if (yy >= 0 && yy < HGT && xx >= 0 && xx < WID)
                v = x[((b * CHN + c) * HGT + yy) * WID + xx];
            sm[OFF_XS + i] = v;
        }
        __syncthreads();

        // ---- features (x, sobel-x, sobel-y) -> BUF0 as tf32 A-matrix [64 x 48] ----
        for (int idx = tid; idx < CHN * TPX; idx += NTHREADS) {
            const int i = idx & (TPX - 1);
            const int c = idx >> 6;
            const float* xr = &sm[OFF_XS + c * 3 * XS_ROW];
            float x00 = xr[i],            x01 = xr[i + 1],            x02 = xr[i + 2];
            float x10 = xr[XS_ROW + i],   x11 = xr[XS_ROW + i + 1],   x12 = xr[XS_ROW + i + 2];
            float x20 = xr[2*XS_ROW + i], x21 = xr[2*XS_ROW + i + 1], x22 = xr[2*XS_ROW + i + 2];
            float gx = (x02 - x00) + 2.f * (x12 - x10) + (x22 - x20);
            float gy = (x20 - x00) + 2.f * (x21 - x01) + (x22 - x02);
            unsigned* dst = &smu[OFF_BUF0 + i * SWS];
            dst[c]           = f2tf(x11);
            dst[CHN + c]     = f2tf(gx);
            dst[2 * CHN + c] = f2tf(gy);
        }
        // ---- sel mask: fire && (3x3 maxpool of alpha > 0.1) ----
        if (tid < TPX) {
            const int i = tid;
            const float* ar = &sm[OFF_XS + 3 * 3 * XS_ROW];  // channel 3
            float m = ar[i];
            m = fmaxf(m, ar[i + 1]);
            m = fmaxf(m, ar[i + 2]);
            m = fmaxf(m, ar[XS_ROW + i]);
            m = fmaxf(m, ar[XS_ROW + i + 1]);
            m = fmaxf(m, ar[XS_ROW + i + 2]);
            m = fmaxf(m, ar[2 * XS_ROW + i]);
            m = fmaxf(m, ar[2 * XS_ROW + i + 1]);
            m = fmaxf(m, ar[2 * XS_ROW + i + 2]);
            float fire = fm[(b * HGT + y) * WID + w0 + i];
            sm[OFF_SEL + i] = (m > 0.1f && fire != 0.f) ? 1.f : 0.f;
        }
        __syncthreads();

        // ---- layer 1: BUF0[64x48] @ W1[48x128] -> BUF1 ----
        gemm_layer<6>(&smu[OFF_BUF0], &smu[OFF_W1], &sm[OFF_B1], &smu[OFF_BUF1],
                      rowBase, colBase, g, tq);
        __syncthreads();

        // ---- layer 2: BUF1[64x128] @ W2[128x128] -> BUF0 ----
        gemm_layer<16>(&smu[OFF_BUF1], &smu[OFF_W2], &sm[OFF_B2], &smu[OFF_BUF0],
                       rowBase, colBase, g, tq);
        __syncthreads();

        // ---- layer 3: BUF0[64x128] @ W3[128x16] -> u * sel -> out ----
        {
            float acc[4] = {0.f, 0.f, 0.f, 0.f};
            const int n0 = warpN * 8;    // each warpN-half owns 8 of 16 out channels
#pragma unroll
            for (int kt = 0; kt < 16; kt++) {
                const int k0 = kt * 8;
                unsigned a0 = smu[OFF_BUF0 + (rowBase + g)     * SWS + k0 + tq];
                unsigned a1 = smu[OFF_BUF0 + (rowBase + g + 8) * SWS + k0 + tq];
                unsigned a2 = smu[OFF_BUF0 + (rowBase + g)     * SWS + k0 + tq + 4];
                unsigned a3 = smu[OFF_BUF0 + (rowBase + g + 8) * SWS + k0 + tq + 4];
                unsigned bb0 = smu[OFF_W3 + (k0 + tq)     * SW3 + n0 + g];
                unsigned bb1 = smu[OFF_W3 + (k0 + tq + 4) * SW3 + n0 + g];
                mma_tf32(acc, a0, a1, a2, a3, bb0, bb1);
            }
            const int c0 = n0 + 2 * tq;
            const int i0 = rowBase + g;
            const float s0 = sm[OFF_SEL + i0];
            const float s1 = sm[OFF_SEL + i0 + 8];
            const float bb0 = sm[OFF_B3 + c0], bb1 = sm[OFF_B3 + c0 + 1];
            float u0 = (acc[0] + bb0) * s0;
            float u1 = (acc[1] + bb1) * s0;
            float u2 = (acc[2] + bb0) * s1;
            float u3 = (acc[3] + bb1) * s1;
            out[((b * CHN + c0)     * HGT + y) * WID + w0 + i0]     = u0;
            out[((b * CHN + c0 + 1) * HGT + y) * WID + w0 + i0]     = u1;
            out[((b * CHN + c0)     * HGT + y) * WID + w0 + i0 + 8] = u2;
            out[((b * CHN + c0 + 1) * HGT + y) * WID + w0 + i0 + 8] = u3;
        }
        __syncthreads();   // protect BUF/XS/SEL before next tile
    }
}

// ---------------- launch ----------------
extern "C" void kernel_launch(void* const* d_in, const int* in_sizes, int n_in,
                              void* d_out, int out_size) {
    const float* x  = (const float*)d_in[0];
    const float* fm = (const float*)d_in[1];
    const float* w1 = (const float*)d_in[2];
    const float* b1 = (const float*)d_in[3];
    const float* w2 = (const float*)d_in[4];
    const float* b2 = (const float*)d_in[5];
    const float* w3 = (const float*)d_in[6];
    const float* b3 = (const float*)d_in[7];
    float* out = (float*)d_out;

    (void)in_sizes; (void)n_in; (void)out_size;

    int dev = 0;
    cudaGetDevice(&dev);
    int sms = 148;
    cudaDeviceGetAttribute(&sms, cudaDevAttrMultiProcessorCount, dev);

    cudaFuncSetAttribute(nca_kernel, cudaFuncAttributeMaxDynamicSharedMemorySize, SMEM_BYTES);
    nca_kernel<<<sms, NTHREADS, SMEM_BYTES>>>(x, fm, w1, b1, w2, b2, w3, b3, out);
}

// round 3
// speedup vs baseline: 1.6329x; 1.6329x over previous
#include <cuda_runtime.h>

// ---------------- problem constants ----------------
#define CHN   16
#define EMB   128
#define KF    48            // 3*CHN input features
#define HGT   256
#define WID   256
#define BATCH 16
#define TPX   128           // pixels per tile (contiguous along W)
#define TILES_PER_ROW (WID / TPX)            // 2
#define TILES_PER_IMG (HGT * TILES_PER_ROW)  // 512
#define NT    (BATCH * TILES_PER_IMG)        // 8192
#define NTHREADS 512

// ---------------- shared memory layout (float offsets) ----------------
// strides chosen so that per-warp fragment loads hit 32 distinct banks:
//   A-operand: addr = row*stride + (k0+tq); B-operand: addr = (n0+g)*stride + (k0+tq)
//   stride % 32 == 4 (132) or == 20 (52)  -> bank = (4g+tq) / (20g+tq): conflict-free
#define SF  52                  // stride for F and W1T (48 + pad 4)
#define SW  132                 // stride for H, W2T, W3T (128 + pad 4)

#define OFF_W1T  0                              // [128 out][52]  (tf32 bits)
#define OFF_W2T  (OFF_W1T + EMB * SF)           // [128 out][132]
#define OFF_W3T  (OFF_W2T + EMB * SW)           // [16 out][132]
#define OFF_B1   (OFF_W3T + CHN * SW)
#define OFF_B2   (OFF_B1 + EMB)
#define OFF_B3   (OFF_B2 + EMB)
#define OFF_F    (OFF_B3 + CHN)                 // [128 px][52]   features (A of L1)
#define OFF_H    (OFF_F + TPX * SF)             // [128 px][132]  activations (in-place L2)
#define XS_ROW   (TPX + 2)                      // 130
#define OFF_XS   (OFF_H + TPX * SW)             // [16 ch][3 rows][130]
#define OFF_SEL  (OFF_XS + CHN * 3 * XS_ROW)
#define SMEM_FLOATS (OFF_SEL + TPX)
#define SMEM_BYTES  (SMEM_FLOATS * 4)           // 223,424 B

// ---------------- helpers ----------------
__device__ __forceinline__ unsigned f2tf(float f) {
    unsigned r;
    asm("cvt.rna.tf32.f32 %0, %1;" : "=r"(r) : "f"(f));
    return r;
}

__device__ __forceinline__ void mma_tf32(float* d,
                                         unsigned a0, unsigned a1, unsigned a2, unsigned a3,
                                         unsigned b0, unsigned b1) {
    asm volatile(
        "mma.sync.aligned.m16n8k8.row.col.f32.tf32.tf32.f32 "
        "{%0,%1,%2,%3}, {%4,%5,%6,%7}, {%8,%9}, {%0,%1,%2,%3};\n"
        : "+f"(d[0]), "+f"(d[1]), "+f"(d[2]), "+f"(d[3])
        : "r"(a0), "r"(a1), "r"(a2), "r"(a3), "r"(b0), "r"(b1));
}

// Warp-tile 32x32 accumulate: acc[2 mtiles][4 ntiles][4]
// A: [rows][AS] row-major tf32 bits; Bt: [out][BS] (transposed weights) tf32 bits
template <int KT, int AS, int BS>
__device__ __forceinline__ void gemm_acc(const unsigned* __restrict__ A,
                                         const unsigned* __restrict__ Bt,
                                         float acc[2][4][4],
                                         int rowBase, int colBase, int g, int tq) {
#pragma unroll
    for (int kt = 0; kt < KT; kt++) {
        const int k0 = kt * 8;
        unsigned a[2][4];
#pragma unroll
        for (int m = 0; m < 2; m++) {
            const int r0 = rowBase + 16 * m + g;
            a[m][0] = A[r0       * AS + k0 + tq];
            a[m][1] = A[(r0 + 8) * AS + k0 + tq];
            a[m][2] = A[r0       * AS + k0 + tq + 4];
            a[m][3] = A[(r0 + 8) * AS + k0 + tq + 4];
        }
#pragma unroll
        for (int n = 0; n < 4; n++) {
            const int nr = colBase + 8 * n + g;
            unsigned b0 = Bt[nr * BS + k0 + tq];
            unsigned b1 = Bt[nr * BS + k0 + tq + 4];
#pragma unroll
            for (int m = 0; m < 2; m++)
                mma_tf32(acc[m][n], a[m][0], a[m][1], a[m][2], a[m][3], b0, b1);
        }
    }
}

// bias + relu + tf32 store of a 32x32 warp tile into Out (stride SW)
__device__ __forceinline__ void epi_relu(float acc[2][4][4], const float* __restrict__ bias,
                                         unsigned* __restrict__ Out,
                                         int rowBase, int colBase, int g, int tq) {
#pragma unroll
    for (int m = 0; m < 2; m++) {
        const int r0 = rowBase + 16 * m + g;
#pragma unroll
        for (int n = 0; n < 4; n++) {
            const int c0 = colBase + 8 * n + 2 * tq;
            const float bb0 = bias[c0], bb1 = bias[c0 + 1];
            Out[r0       * SW + c0]     = f2tf(fmaxf(acc[m][n][0] + bb0, 0.f));
            Out[r0       * SW + c0 + 1] = f2tf(fmaxf(acc[m][n][1] + bb1, 0.f));
            Out[(r0 + 8) * SW + c0]     = f2tf(fmaxf(acc[m][n][2] + bb0, 0.f));
            Out[(r0 + 8) * SW + c0 + 1] = f2tf(fmaxf(acc[m][n][3] + bb1, 0.f));
        }
    }
}

// ---------------- kernel ----------------
__global__ void __launch_bounds__(NTHREADS, 1)
nca_kernel(const float* __restrict__ x,  const float* __restrict__ fm,
           const float* __restrict__ w1, const float* __restrict__ b1,
           const float* __restrict__ w2, const float* __restrict__ b2,
           const float* __restrict__ w3, const float* __restrict__ b3,
           float* __restrict__ out) {
    extern __shared__ float sm[];
    unsigned* smu = reinterpret_cast<unsigned*>(sm);

    const int tid  = threadIdx.x;
    const int lane = tid & 31;
    const int wid  = tid >> 5;
    const int g    = lane >> 2;      // 0..7
    const int tq   = lane & 3;       // 0..3
    // L1/L2 tiling: 16 warps = 4 over M(32 rows) x 4 over N(32 cols)
    const int rowBase = (wid & 3) * 32;
    const int colBase = (wid >> 2) * 32;
    // L3 tiling: 8 over M(16 rows) x 2 over N(8 cols)
    const int rowBase3 = (wid & 7) * 16;
    const int n03      = (wid >> 3) * 8;

    // ---- stage weights transposed [out][in] as tf32 (once per CTA) ----
    for (int i = tid; i < KF * EMB; i += NTHREADS) {
        const int k = i >> 7, n = i & 127;
        smu[OFF_W1T + n * SF + k] = f2tf(w1[i]);
    }
    for (int i = tid; i < EMB * EMB; i += NTHREADS) {
        const int k = i >> 7, n = i & 127;
        smu[OFF_W2T + n * SW + k] = f2tf(w2[i]);
    }
    for (int i = tid; i < EMB * CHN; i += NTHREADS) {
        const int k = i >> 4, n = i & 15;
        smu[OFF_W3T + n * SW + k] = f2tf(w3[i]);
    }
    for (int i = tid; i < EMB; i += NTHREADS) {
        sm[OFF_B1 + i] = b1[i];
        sm[OFF_B2 + i] = b2[i];
    }
    if (tid < CHN) sm[OFF_B3 + tid] = b3[tid];
    __syncthreads();

    for (int t = blockIdx.x; t < NT; t += gridDim.x) {
        const int b   = t >> 9;            // TILES_PER_IMG = 512
        const int rem = t & 511;
        const int y   = rem >> 1;          // TILES_PER_ROW = 2
        const int w0  = (rem & 1) << 7;

        // ---- stage x halo: 16ch x 3rows x 130cols, zero-padded ----
        for (int i = tid; i < CHN * 3 * XS_ROW; i += NTHREADS) {
            const int c   = i / (3 * XS_ROW);
            const int r2  = i - c * 3 * XS_ROW;
            const int dy  = r2 / XS_ROW;
            const int col = r2 - dy * XS_ROW;
            const int yy = y + dy - 1;
            const int xx = w0 + col - 1;
            float v = 0.f;
            if (yy >= 0 && yy < HGT && xx >= 0 && xx < WID)
                v = x[((b * CHN + c) * HGT + yy) * WID + xx];
            sm[OFF_XS + i] = v;
        }
        __syncthreads();

        // ---- features (x, sobel-x, sobel-y) -> F[128 x 48] tf32 ----
        for (int idx = tid; idx < CHN * TPX; idx += NTHREADS) {
            const int i = idx & (TPX - 1);
            const int c = idx >> 7;
            const float* xr = &sm[OFF_XS + c * 3 * XS_ROW];
            float x00 = xr[i],              x01 = xr[i + 1],              x02 = xr[i + 2];
            float x10 = xr[XS_ROW + i],     x11 = xr[XS_ROW + i + 1],     x12 = xr[XS_ROW + i + 2];
            float x20 = xr[2 * XS_ROW + i], x21 = xr[2 * XS_ROW + i + 1], x22 = xr[2 * XS_ROW + i + 2];
            float gx = (x02 - x00) + 2.f * (x12 - x10) + (x22 - x20);
            float gy = (x20 - x00) + 2.f * (x21 - x01) + (x22 - x02);
            unsigned* dst = &smu[OFF_F + i * SF];
            dst[c]           = f2tf(x11);
            dst[CHN + c]     = f2tf(gx);
            dst[2 * CHN + c] = f2tf(gy);
        }
        // ---- sel mask: fire && (3x3 maxpool of alpha > 0.1) ----
        if (tid < TPX) {
            const int i = tid;
            const float* ar = &sm[OFF_XS + 3 * 3 * XS_ROW];  // channel 3
            float m = ar[i];
            m = fmaxf(m, ar[i + 1]);
            m = fmaxf(m, ar[i + 2]);
            m = fmaxf(m, ar[XS_ROW + i]);
            m = fmaxf(m, ar[XS_ROW + i + 1]);
            m = fmaxf(m, ar[XS_ROW + i + 2]);
            m = fmaxf(m, ar[2 * XS_ROW + i]);
            m = fmaxf(m, ar[2 * XS_ROW + i + 1]);
            m = fmaxf(m, ar[2 * XS_ROW + i + 2]);
            float fire = fm[(b * HGT + y) * WID + w0 + i];
            sm[OFF_SEL + i] = (m > 0.1f && fire != 0.f) ? 1.f : 0.f;
        }
        __syncthreads();

        // ---- layer 1: F[128x48] @ W1 -> H[128x128] ----
        {
            float acc[2][4][4];
#pragma unroll
            for (int m = 0; m < 2; m++)
#pragma unroll
                for (int n = 0; n < 4; n++)
#pragma unroll
                    for (int j = 0; j < 4; j++) acc[m][n][j] = 0.f;
            gemm_acc<6, SF, SF>(&smu[OFF_F], &smu[OFF_W1T], acc, rowBase, colBase, g, tq);
            epi_relu(acc, &sm[OFF_B1], &smu[OFF_H], rowBase, colBase, g, tq);
        }
        __syncthreads();   // H fully written

        // ---- layer 2: H[128x128] @ W2 -> H (in place) ----
        {
            float acc[2][4][4];
#pragma unroll
            for (int m = 0; m < 2; m++)
#pragma unroll
                for (int n = 0; n < 4; n++)
#pragma unroll
                    for (int j = 0; j < 4; j++) acc[m][n][j] = 0.f;
            gemm_acc<16, SW, SW>(&smu[OFF_H], &smu[OFF_W2T], acc, rowBase, colBase, g, tq);
            __syncthreads();   // everyone done READING H before in-place overwrite
            epi_relu(acc, &sm[OFF_B2], &smu[OFF_H], rowBase, colBase, g, tq);
        }
        __syncthreads();   // H (layer-2 output) fully written

        // ---- layer 3: H[128x128] @ W3[->16] * sel -> out ----
        {
            float acc[4] = {0.f, 0.f, 0.f, 0.f};
#pragma unroll
            for (int kt = 0; kt < 16; kt++) {
                const int k0 = kt * 8;
                unsigned a0 = smu[OFF_H + (rowBase3 + g)     * SW + k0 + tq];
                unsigned a1 = smu[OFF_H + (rowBase3 + g + 8) * SW + k0 + tq];
                unsigned a2 = smu[OFF_H + (rowBase3 + g)     * SW + k0 + tq + 4];
                unsigned a3 = smu[OFF_H + (rowBase3 + g + 8) * SW + k0 + tq + 4];
                unsigned b0 = smu[OFF_W3T + (n03 + g) * SW + k0 + tq];
                unsigned b1 = smu[OFF_W3T + (n03 + g) * SW + k0 + tq + 4];
                mma_tf32(acc, a0, a1, a2, a3, b0, b1);
            }
            const int c0 = n03 + 2 * tq;
            const int i0 = rowBase3 + g;
            const float s0 = sm[OFF_SEL + i0];
            const float s1 = sm[OFF_SEL + i0 + 8];
            const float bb0 = sm[OFF_B3 + c0], bb1 = sm[OFF_B3 + c0 + 1];
            out[((b * CHN + c0)     * HGT + y) * WID + w0 + i0]     = (acc[0] + bb0) * s0;
            out[((b * CHN + c0 + 1) * HGT + y) * WID + w0 + i0]     = (acc[1] + bb1) * s0;
            out[((b * CHN + c0)     * HGT + y) * WID + w0 + i0 + 8] = (acc[2] + bb0) * s1;
            out[((b * CHN + c0 + 1) * HGT + y) * WID + w0 + i0 + 8] = (acc[3] + bb1) * s1;
        }
        __syncthreads();   // protect XS/F/H/SEL before next tile
    }
}

// ---------------- launch ----------------
extern "C" void kernel_launch(void* const* d_in, const int* in_sizes, int n_in,
                              void* d_out, int out_size) {
    const float* x  = (const float*)d_in[0];
    const float* fm = (const float*)d_in[1];
    const float* w1 = (const float*)d_in[2];
    const float* b1 = (const float*)d_in[3];
    const float* w2 = (const float*)d_in[4];
    const float* b2 = (const float*)d_in[5];
    const float* w3 = (const float*)d_in[6];
    const float* b3 = (const float*)d_in[7];
    float* out = (float*)d_out;

    (void)in_sizes; (void)n_in; (void)out_size;

    int dev = 0;
    cudaGetDevice(&dev);
    int sms = 148;
    cudaDeviceGetAttribute(&sms, cudaDevAttrMultiProcessorCount, dev);

    cudaFuncSetAttribute(nca_kernel, cudaFuncAttributeMaxDynamicSharedMemorySize, SMEM_BYTES);
    nca_kernel<<<sms, NTHREADS, SMEM_BYTES>>>(x, fm, w1, b1, w2, b2, w3, b3, out);
}

// round 6
// speedup vs baseline: 2.0822x; 1.2752x over previous
#include <cuda_runtime.h>

// ---------------- problem constants ----------------
#define CHN   16
#define EMB   128
#define KF    48            // 3*CHN input features
#define HGT   256
#define WID   256
#define BATCH 16
#define POOLW 256           // pool = one full image row
#define NPOOL (BATCH * HGT) // 4096
#define NTHREADS 512

// ---------------- shared memory layout (float offsets) ----------------
// strides % 32 == 4 (132) or 20 (52) -> warp fragment loads hit 32 distinct banks
#define SF  52                  // stride for F and W1T (48 + pad)
#define SW  132                 // stride for H, W2T, W3T (128 + pad)

#define OFF_W1T  0                              // [128 out][52]  tf32 bits
#define OFF_W2T  (OFF_W1T + EMB * SF)           // [128 out][132]
#define OFF_W3T  (OFF_W2T + EMB * SW)           // [16 out][132]
#define OFF_B1   (OFF_W3T + CHN * SW)
#define OFF_B2   (OFF_B1 + EMB)
#define OFF_B3   (OFF_B2 + EMB)
#define OFF_H    (OFF_B3 + CHN)                 // [128 rows][132] activations
#define OFF_F    OFF_H                          // F lives in-place inside H (sync trick)
#define XS_ROW   (POOLW + 2)                    // 258
#define OFF_XS   (OFF_H + 128 * SW)             // [16 ch][3 rows][258]
#define OFF_LIVE (OFF_XS + CHN * 3 * XS_ROW)    // [256] int flags
#define OFF_IDX  (OFF_LIVE + POOLW)             // [256] int compact indices
#define OFF_CNT  (OFF_IDX + POOLW)              // [8] warp counts -> bases
#define OFF_NL   (OFF_CNT + 8)
#define SMEM_FLOATS (OFF_NL + 1)
#define SMEM_BYTES  (SMEM_FLOATS * 4)           // ~222.9 KB

// ---------------- helpers ----------------
__device__ __forceinline__ unsigned f2tf(float f) {
    unsigned r;
    asm("cvt.rna.tf32.f32 %0, %1;" : "=r"(r) : "f"(f));
    return r;
}

__device__ __forceinline__ void mma_tf32(float* d,
                                         unsigned a0, unsigned a1, unsigned a2, unsigned a3,
                                         unsigned b0, unsigned b1) {
    asm volatile(
        "mma.sync.aligned.m16n8k8.row.col.f32.tf32.tf32.f32 "
        "{%0,%1,%2,%3}, {%4,%5,%6,%7}, {%8,%9}, {%0,%1,%2,%3};\n"
        : "+f"(d[0]), "+f"(d[1]), "+f"(d[2]), "+f"(d[3])
        : "r"(a0), "r"(a1), "r"(a2), "r"(a3), "r"(b0), "r"(b1));
}

// Warp-tile 32x32 accumulate: acc[2 mtiles][4 ntiles][4]
template <int KT, int AS, int BS>
__device__ __forceinline__ void gemm_acc(const unsigned* __restrict__ A,
                                         const unsigned* __restrict__ Bt,
                                         float acc[2][4][4],
                                         int rowBase, int colBase, int g, int tq) {
#pragma unroll
    for (int kt = 0; kt < KT; kt++) {
        const int k0 = kt * 8;
        unsigned a[2][4];
#pragma unroll
        for (int m = 0; m < 2; m++) {
            const int r0 = rowBase + 16 * m + g;
            a[m][0] = A[r0       * AS + k0 + tq];
            a[m][1] = A[(r0 + 8) * AS + k0 + tq];
            a[m][2] = A[r0       * AS + k0 + tq + 4];
            a[m][3] = A[(r0 + 8) * AS + k0 + tq + 4];
        }
#pragma unroll
        for (int n = 0; n < 4; n++) {
            const int nr = colBase + 8 * n + g;
            unsigned b0 = Bt[nr * BS + k0 + tq];
            unsigned b1 = Bt[nr * BS + k0 + tq + 4];
#pragma unroll
            for (int m = 0; m < 2; m++)
                mma_tf32(acc[m][n], a[m][0], a[m][1], a[m][2], a[m][3], b0, b1);
        }
    }
}

__device__ __forceinline__ void epi_relu(float acc[2][4][4], const float* __restrict__ bias,
                                         unsigned* __restrict__ Out,
                                         int rowBase, int colBase, int g, int tq) {
#pragma unroll
    for (int m = 0; m < 2; m++) {
        const int r0 = rowBase + 16 * m + g;
#pragma unroll
        for (int n = 0; n < 4; n++) {
            const int c0 = colBase + 8 * n + 2 * tq;
            const float bb0 = bias[c0], bb1 = bias[c0 + 1];
            Out[r0       * SW + c0]     = f2tf(fmaxf(acc[m][n][0] + bb0, 0.f));
            Out[r0       * SW + c0 + 1] = f2tf(fmaxf(acc[m][n][1] + bb1, 0.f));
            Out[(r0 + 8) * SW + c0]     = f2tf(fmaxf(acc[m][n][2] + bb0, 0.f));
            Out[(r0 + 8) * SW + c0 + 1] = f2tf(fmaxf(acc[m][n][3] + bb1, 0.f));
        }
    }
}

// ---------------- kernel ----------------
__global__ void __launch_bounds__(NTHREADS, 1)
nca_kernel(const float* __restrict__ x,  const float* __restrict__ fm,
           const float* __restrict__ w1, const float* __restrict__ b1,
           const float* __restrict__ w2, const float* __restrict__ b2,
           const float* __restrict__ w3, const float* __restrict__ b3,
           float* __restrict__ out) {
    extern __shared__ float sm[];
    unsigned* smu = reinterpret_cast<unsigned*>(sm);
    int*      smi = reinterpret_cast<int*>(sm);

    const int tid  = threadIdx.x;
    const int lane = tid & 31;
    const int wid  = tid >> 5;
    const int g    = lane >> 2;      // 0..7
    const int tq   = lane & 3;       // 0..3
    // L1/L2 tiling: 16 warps = 4 over M(32 rows) x 4 over N(32 cols)
    const int rowBase = (wid & 3) * 32;
    const int colBase = (wid >> 2) * 32;
    // L3 tiling: 8 over M(16 rows) x 2 over N(8 cols)
    const int rowBase3 = (wid & 7) * 16;
    const int n03      = (wid >> 3) * 8;

    // ---- stage weights transposed [out][in] as tf32 (once per CTA) ----
    for (int i = tid; i < KF * EMB; i += NTHREADS) {
        const int k = i >> 7, n = i & 127;
        smu[OFF_W1T + n * SF + k] = f2tf(w1[i]);
    }
    for (int i = tid; i < EMB * EMB; i += NTHREADS) {
        const int k = i >> 7, n = i & 127;
        smu[OFF_W2T + n * SW + k] = f2tf(w2[i]);
    }
    for (int i = tid; i < EMB * CHN; i += NTHREADS) {
        const int k = i >> 4, n = i & 15;
        smu[OFF_W3T + n * SW + k] = f2tf(w3[i]);
    }
    for (int i = tid; i < EMB; i += NTHREADS) {
        sm[OFF_B1 + i] = b1[i];
        sm[OFF_B2 + i] = b2[i];
    }
    if (tid < CHN) sm[OFF_B3 + tid] = b3[tid];
    __syncthreads();

    for (int t = blockIdx.x; t < NPOOL; t += gridDim.x) {
        const int b = t >> 8;
        const int y = t & 255;

        // ---- stage x halo: 16ch x 3rows x 258 cols, zero-padded ----
        for (int i = tid; i < CHN * 3 * XS_ROW; i += NTHREADS) {
            const int c   = i / (3 * XS_ROW);
            const int r2  = i - c * 3 * XS_ROW;
            const int dy  = r2 / XS_ROW;
            const int col = r2 - dy * XS_ROW;
            const int yy = y + dy - 1;
            const int xx = col - 1;
            float v = 0.f;
            if (yy >= 0 && yy < HGT && xx >= 0 && xx < WID)
                v = x[((b * CHN + c) * HGT + yy) * WID + xx];
            sm[OFF_XS + i] = v;
        }
        __syncthreads();

        // ---- sel mask + warp ballot counts ----
        unsigned bal = 0;
        int live = 0;
        if (tid < POOLW) {
            const int i = tid;
            const float* ar = &sm[OFF_XS + 3 * 3 * XS_ROW];  // channel 3 (alpha)
            float m = ar[i];
            m = fmaxf(m, ar[i + 1]);
            m = fmaxf(m, ar[i + 2]);
            m = fmaxf(m, ar[XS_ROW + i]);
            m = fmaxf(m, ar[XS_ROW + i + 1]);
            m = fmaxf(m, ar[XS_ROW + i + 2]);
            m = fmaxf(m, ar[2 * XS_ROW + i]);
            m = fmaxf(m, ar[2 * XS_ROW + i + 1]);
            m = fmaxf(m, ar[2 * XS_ROW + i + 2]);
            float fire = fm[(b * HGT + y) * WID + i];
            live = (m > 0.1f && fire != 0.f) ? 1 : 0;
            smi[OFF_LIVE + i] = live;
            bal = __ballot_sync(0xffffffffu, live);
            if (lane == 0) smi[OFF_CNT + wid] = __popc(bal);
        }
        __syncthreads();
        if (tid == 0) {
            int s = 0;
#pragma unroll
            for (int w2_ = 0; w2_ < 8; w2_++) {
                int c = smi[OFF_CNT + w2_];
                smi[OFF_CNT + w2_] = s;
                s += c;
            }
            smi[OFF_NL] = s;
        }
        __syncthreads();
        if (tid < POOLW && live)
            smi[OFF_IDX + smi[OFF_CNT + wid] + __popc(bal & ((1u << lane) - 1))] = tid;
        // zero dead outputs
        for (int i = tid; i < POOLW * CHN; i += NTHREADS) {
            const int p = i & 255, c = i >> 8;
            if (!smi[OFF_LIVE + p])
                out[((b * CHN + c) * HGT + y) * WID + p] = 0.f;
        }
        __syncthreads();
        const int NL = smi[OFF_NL];

        // ---- compacted GEMM chunks of up to 128 rows ----
        for (int base = 0; base < NL; base += 128) {
            const int rows = min(128, NL - base);
            const int rows_pad = (rows + 31) & ~31;

            // features for live rows -> F (in-place in H region), tf32
            for (int j = tid; j < rows * CHN; j += NTHREADS) {
                const int r = j >> 4, c = j & 15;
                const int p = smi[OFF_IDX + base + r];
                const float* xr = &sm[OFF_XS + c * 3 * XS_ROW];
                float x00 = xr[p],              x01 = xr[p + 1],              x02 = xr[p + 2];
                float x10 = xr[XS_ROW + p],     x11 = xr[XS_ROW + p + 1],     x12 = xr[XS_ROW + p + 2];
                float x20 = xr[2 * XS_ROW + p], x21 = xr[2 * XS_ROW + p + 1], x22 = xr[2 * XS_ROW + p + 2];
                float gx = (x02 - x00) + 2.f * (x12 - x10) + (x22 - x20);
                float gy = (x20 - x00) + 2.f * (x21 - x01) + (x22 - x02);
                unsigned* dst = &smu[OFF_F + r * SF];
                dst[c]           = f2tf(x11);
                dst[CHN + c]     = f2tf(gx);
                dst[2 * CHN + c] = f2tf(gy);
            }
            // zero-pad F tail rows of the last active band (avoid NaN garbage)
            for (int j = tid; j < (rows_pad - rows) * SF; j += NTHREADS)
                smu[OFF_F + rows * SF + j] = 0u;
            __syncthreads();

            const bool act12 = (rowBase < rows);

            // ---- layer 1: F[rows x 48] @ W1 -> H (in place over F) ----
            {
                float acc[2][4][4];
#pragma unroll
                for (int m = 0; m < 2; m++)
#pragma unroll
                    for (int n = 0; n < 4; n++)
#pragma unroll
                        for (int j = 0; j < 4; j++) acc[m][n][j] = 0.f;
                if (act12)
                    gemm_acc<6, SF, SF>(&smu[OFF_F], &smu[OFF_W1T], acc, rowBase, colBase, g, tq);
                __syncthreads();   // all reads of F done before overwrite
                if (act12)
                    epi_relu(acc, &sm[OFF_B1], &smu[OFF_H], rowBase, colBase, g, tq);
            }
            __syncthreads();

            // ---- layer 2: H @ W2 -> H (in place) ----
            {
                float acc[2][4][4];
#pragma unroll
                for (int m = 0; m < 2; m++)
#pragma unroll
                    for (int n = 0; n < 4; n++)
#pragma unroll
                        for (int j = 0; j < 4; j++) acc[m][n][j] = 0.f;
                if (act12)
                    gemm_acc<16, SW, SW>(&smu[OFF_H], &smu[OFF_W2T], acc, rowBase, colBase, g, tq);
                __syncthreads();
                if (act12)
                    epi_relu(acc, &sm[OFF_B2], &smu[OFF_H], rowBase, colBase, g, tq);
            }
            __syncthreads();

            // ---- layer 3: H @ W3[->16] -> scatter to out (sel==1 for all rows) ----
            if (rowBase3 < rows) {
                float acc[4] = {0.f, 0.f, 0.f, 0.f};
#pragma unroll
                for (int kt = 0; kt < 16; kt++) {
                    const int k0 = kt * 8;
                    unsigned a0 = smu[OFF_H + (rowBase3 + g)     * SW + k0 + tq];
                    unsigned a1 = smu[OFF_H + (rowBase3 + g + 8) * SW + k0 + tq];
                    unsigned a2 = smu[OFF_H + (rowBase3 + g)     * SW + k0 + tq + 4];
                    unsigned a3 = smu[OFF_H + (rowBase3 + g + 8) * SW + k0 + tq + 4];
                    unsigned b0 = smu[OFF_W3T + (n03 + g) * SW + k0 + tq];
                    unsigned b1 = smu[OFF_W3T + (n03 + g) * SW + k0 + tq + 4];
                    mma_tf32(acc, a0, a1, a2, a3, b0, b1);
                }
                const int c0 = n03 + 2 * tq;
                const int i0 = rowBase3 + g;
                const int i1 = i0 + 8;
                const float bb0 = sm[OFF_B3 + c0], bb1 = sm[OFF_B3 + c0 + 1];
                if (i0 < rows) {
                    const int p = smi[OFF_IDX + base + i0];
                    out[((b * CHN + c0)     * HGT + y) * WID + p] = acc[0] + bb0;
                    out[((b * CHN + c0 + 1) * HGT + y) * WID + p] = acc[1] + bb1;
                }
                if (i1 < rows) {
                    const int p = smi[OFF_IDX + base + i1];
                    out[((b * CHN + c0)     * HGT + y) * WID + p] = acc[2] + bb0;
                    out[((b * CHN + c0 + 1) * HGT + y) * WID + p] = acc[3] + bb1;
                }
            }
            __syncthreads();   // H/F reuse next chunk
        }
        __syncthreads();       // XS/LIVE/IDX reuse next pool
    }
}

// ---------------- launch ----------------
extern "C" void kernel_launch(void* const* d_in, const int* in_sizes, int n_in,
                              void* d_out, int out_size) {
    const float* x  = (const float*)d_in[0];
    const float* fm = (const float*)d_in[1];
    const float* w1 = (const float*)d_in[2];
    const float* b1 = (const float*)d_in[3];
    const float* w2 = (const float*)d_in[4];
    const float* b2 = (const float*)d_in[5];
    const float* w3 = (const float*)d_in[6];
    const float* b3 = (const float*)d_in[7];
    float* out = (float*)d_out;

    (void)in_sizes; (void)n_in; (void)out_size;

    int dev = 0;
    cudaGetDevice(&dev);
    int sms = 148;
    cudaDeviceGetAttribute(&sms, cudaDevAttrMultiProcessorCount, dev);

    cudaFuncSetAttribute(nca_kernel, cudaFuncAttributeMaxDynamicSharedMemorySize, SMEM_BYTES);
    nca_kernel<<<sms, NTHREADS, SMEM_BYTES>>>(x, fm, w1, b1, w2, b2, w3, b3, out);
}

// round 10
// speedup vs baseline: 2.2699x; 1.0901x over previous
#include <cuda_runtime.h>

// ---------------- problem constants ----------------
#define CHN   16
#define EMB   128
#define KF    48            // 3*CHN input features
#define HGT   256
#define WID   256
#define BATCH 16
#define POOLW 256           // pool = one full image row
#define NPOOL (BATCH * HGT) // 4096
#define NTHREADS 512

// ---------------- shared memory layout (float offsets) ----------------
// strides % 32 == 4 (132) or 20 (52) -> warp fragment loads hit 32 distinct banks
#define SF  52                  // stride for F and W1T (48 + pad)
#define SW  132                 // stride for H, W2T, W3T (128 + pad)

#define OFF_W1T  0                              // [128 out][52]  tf32 bits
#define OFF_W2T  (OFF_W1T + EMB * SF)           // [128 out][132]
#define OFF_W3T  (OFF_W2T + EMB * SW)           // [16 out][132]
#define OFF_B1   (OFF_W3T + CHN * SW)
#define OFF_B2   (OFF_B1 + EMB)
#define OFF_B3   (OFF_B2 + EMB)
#define OFF_H    (OFF_B3 + CHN)                 // [128 rows][132] activations
#define OFF_F    OFF_H                          // F lives in-place inside H (sync trick)
// XS: 16 ch x 3 rotating row-slots x 264 floats.
// Pixel p of a row lives at +4+p (16B-aligned for cp.async); halo cells +3 and +260
// are constant zero (written once). XS_ROW % 4 == 0 keeps float4 alignment.
#define XS_ROW   264
#define OFF_XS   (OFF_H + 128 * SW)             // %4==0
#define OFF_LIVE (OFF_XS + CHN * 3 * XS_ROW)    // [256] int flags
#define OFF_IDX  (OFF_LIVE + POOLW)             // [256] int compact indices
#define OFF_CNT  (OFF_IDX + POOLW)              // [8] warp counts -> bases
#define OFF_NL   (OFF_CNT + 8)
#define SMEM_FLOATS (OFF_NL + 1)
#define SMEM_BYTES  (SMEM_FLOATS * 4)           // ~224.1 KB

// ---------------- helpers ----------------
__device__ __forceinline__ unsigned f2tf(float f) {
    unsigned r;
    asm("cvt.rna.tf32.f32 %0, %1;" : "=r"(r) : "f"(f));
    return r;
}

__device__ __forceinline__ void cp16(float* dst, const float* src) {
    unsigned d = (unsigned)__cvta_generic_to_shared(dst);
    asm volatile("cp.async.cg.shared.global [%0], [%1], 16;\n" :: "r"(d), "l"(src));
}

__device__ __forceinline__ void mma_tf32(float* d,
                                         unsigned a0, unsigned a1, unsigned a2, unsigned a3,
                                         unsigned b0, unsigned b1) {
    asm volatile(
        "mma.sync.aligned.m16n8k8.row.col.f32.tf32.tf32.f32 "
        "{%0,%1,%2,%3}, {%4,%5,%6,%7}, {%8,%9}, {%0,%1,%2,%3};\n"
        : "+f"(d[0]), "+f"(d[1]), "+f"(d[2]), "+f"(d[3])
        : "r"(a0), "r"(a1), "r"(a2), "r"(a3), "r"(b0), "r"(b1));
}

// Warp-tile 32x32 accumulate: acc[2 mtiles][4 ntiles][4]
template <int KT, int AS, int BS>
__device__ __forceinline__ void gemm_acc(const unsigned* __restrict__ A,
                                         const unsigned* __restrict__ Bt,
                                         float acc[2][4][4],
                                         int rowBase, int colBase, int g, int tq) {
#pragma unroll
    for (int kt = 0; kt < KT; kt++) {
        const int k0 = kt * 8;
        unsigned a[2][4];
#pragma unroll
        for (int m = 0; m < 2; m++) {
            const int r0 = rowBase + 16 * m + g;
            a[m][0] = A[r0       * AS + k0 + tq];
            a[m][1] = A[(r0 + 8) * AS + k0 + tq];
            a[m][2] = A[r0       * AS + k0 + tq + 4];
            a[m][3] = A[(r0 + 8) * AS + k0 + tq + 4];
        }
#pragma unroll
        for (int n = 0; n < 4; n++) {
            const int nr = colBase + 8 * n + g;
            unsigned b0 = Bt[nr * BS + k0 + tq];
            unsigned b1 = Bt[nr * BS + k0 + tq + 4];
#pragma unroll
            for (int m = 0; m < 2; m++)
                mma_tf32(acc[m][n], a[m][0], a[m][1], a[m][2], a[m][3], b0, b1);
        }
    }
}

__device__ __forceinline__ void epi_relu(float acc[2][4][4], const float* __restrict__ bias,
                                         unsigned* __restrict__ Out,
                                         int rowBase, int colBase, int g, int tq) {
#pragma unroll
    for (int m = 0; m < 2; m++) {
        const int r0 = rowBase + 16 * m + g;
#pragma unroll
        for (int n = 0; n < 4; n++) {
            const int c0 = colBase + 8 * n + 2 * tq;
            const float bb0 = bias[c0], bb1 = bias[c0 + 1];
            Out[r0       * SW + c0]     = f2tf(fmaxf(acc[m][n][0] + bb0, 0.f));
            Out[r0       * SW + c0 + 1] = f2tf(fmaxf(acc[m][n][1] + bb1, 0.f));
            Out[(r0 + 8) * SW + c0]     = f2tf(fmaxf(acc[m][n][2] + bb0, 0.f));
            Out[(r0 + 8) * SW + c0 + 1] = f2tf(fmaxf(acc[m][n][3] + bb1, 0.f));
        }
    }
}

// ---------------- kernel ----------------
__global__ void __launch_bounds__(NTHREADS, 1)
nca_kernel(const float* __restrict__ x,  const float* __restrict__ fm,
           const float* __restrict__ w1, const float* __restrict__ b1,
           const float* __restrict__ w2, const float* __restrict__ b2,
           const float* __restrict__ w3, const float* __restrict__ b3,
           float* __restrict__ out) {
    extern __shared__ float sm[];
    unsigned* smu = reinterpret_cast<unsigned*>(sm);
    int*      smi = reinterpret_cast<int*>(sm);

    const int tid  = threadIdx.x;
    const int lane = tid & 31;
    const int wid  = tid >> 5;
    const int g    = lane >> 2;      // 0..7
    const int tq   = lane & 3;       // 0..3
    // L1/L2 tiling: 16 warps = 4 over M(32 rows) x 4 over N(32 cols)
    const int rowBase = (wid & 3) * 32;
    const int colBase = (wid >> 2) * 32;
    // L3 tiling: 8 over M(16 rows) x 2 over N(8 cols)
    const int rowBase3 = (wid & 7) * 16;
    const int n03      = (wid >> 3) * 8;

    // ---- stage weights transposed [out][in] as tf32 (once per CTA) ----
    for (int i = tid; i < KF * EMB; i += NTHREADS) {
        const int k = i >> 7, n = i & 127;
        smu[OFF_W1T + n * SF + k] = f2tf(w1[i]);
    }
    for (int i = tid; i < EMB * EMB; i += NTHREADS) {
        const int k = i >> 7, n = i & 127;
        smu[OFF_W2T + n * SW + k] = f2tf(w2[i]);
    }
    for (int i = tid; i < EMB * CHN; i += NTHREADS) {
        const int k = i >> 4, n = i & 15;
        smu[OFF_W3T + n * SW + k] = f2tf(w3[i]);
    }
    for (int i = tid; i < EMB; i += NTHREADS) {
        sm[OFF_B1 + i] = b1[i];
        sm[OFF_B2 + i] = b2[i];
    }
    if (tid < CHN) sm[OFF_B3 + tid] = b3[tid];
    // constant-zero halo columns (+3 and +260 of every (ch,slot) row)
    for (int i = tid; i < CHN * 3; i += NTHREADS) {
        sm[OFF_XS + i * XS_ROW + 3]   = 0.f;
        sm[OFF_XS + i * XS_ROW + 260] = 0.f;
    }
    __syncthreads();

    // ---- strip of contiguous pools for this CTA ----
    const int per = (NPOOL + gridDim.x - 1) / gridDim.x;
    const int t0  = blockIdx.x * per;
    const int t1  = min(t0 + per, NPOOL);

    for (int t = t0; t < t1; t++) {
        const int b = t >> 8;
        const int y = t & 255;

        // ---- stage halo rows into rotating slots (slot = row mod 3) ----
        {
            const int jlo = (t == t0 || y == 0) ? (y - 1) : (y + 1);
            for (int j = jlo; j <= y + 1; j++) {
                const int slot = ((j % 3) + 3) % 3;
                if (j < 0 || j >= HGT) {
                    for (int i = tid; i < CHN * 256; i += NTHREADS) {
                        const int c = i >> 8, col = i & 255;
                        sm[OFF_XS + (c * 3 + slot) * XS_ROW + 4 + col] = 0.f;
                    }
                } else {
                    for (int i = tid; i < CHN * 64; i += NTHREADS) {
                        const int c = i >> 6, q = i & 63;
                        const float* src = &x[((b * CHN + c) * HGT + j) * WID + 4 * q];
                        float* dst = &sm[OFF_XS + (c * 3 + slot) * XS_ROW + 4 + 4 * q];
                        cp16(dst, src);
                    }
                }
            }
            asm volatile("cp.async.commit_group;\n");
            asm volatile("cp.async.wait_group 0;\n" ::: "memory");
        }
        __syncthreads();

        const int st = (y + 2) % 3;   // slot of row y-1
        const int sM = y % 3;         // slot of row y
        const int sb = (y + 1) % 3;   // slot of row y+1

        // ---- sel mask + warp ballot counts ----
        unsigned bal = 0;
        int live = 0;
        if (tid < POOLW) {
            const int p = tid;
            const float* at = &sm[OFF_XS + (3 * 3 + st) * XS_ROW];  // alpha, row y-1
            const float* am = &sm[OFF_XS + (3 * 3 + sM) * XS_ROW];
            const float* ab = &sm[OFF_XS + (3 * 3 + sb) * XS_ROW];
            float m = at[p + 3];
            m = fmaxf(m, at[p + 4]);
            m = fmaxf(m, at[p + 5]);
            m = fmaxf(m, am[p + 3]);
            m = fmaxf(m, am[p + 4]);
            m = fmaxf(m, am[p + 5]);
            m = fmaxf(m, ab[p + 3]);
            m = fmaxf(m, ab[p + 4]);
            m = fmaxf(m, ab[p + 5]);
            float fire = fm[(b * HGT + y) * WID + p];
            live = (m > 0.1f && fire != 0.f) ? 1 : 0;
            smi[OFF_LIVE + p] = live;
            bal = __ballot_sync(0xffffffffu, live);
            if (lane == 0) smi[OFF_CNT + wid] = __popc(bal);
        }
        __syncthreads();
        if (tid == 0) {
            int s = 0;
#pragma unroll
            for (int w2_ = 0; w2_ < 8; w2_++) {
                int c = smi[OFF_CNT + w2_];
                smi[OFF_CNT + w2_] = s;
                s += c;
            }
            smi[OFF_NL] = s;
        }
        __syncthreads();
        if (tid < POOLW && live)
            smi[OFF_IDX + smi[OFF_CNT + wid] + __popc(bal & ((1u << lane) - 1))] = tid;
        // zero dead outputs
        for (int i = tid; i < POOLW * CHN; i += NTHREADS) {
            const int p = i & 255, c = i >> 8;
            if (!smi[OFF_LIVE + p])
                out[((b * CHN + c) * HGT + y) * WID + p] = 0.f;
        }
        __syncthreads();
        const int NL = smi[OFF_NL];

        // ---- compacted GEMM chunks of up to 128 rows ----
        for (int base = 0; base < NL; base += 128) {
            const int rows = min(128, NL - base);
            const int rows_pad = (rows + 31) & ~31;

            // features for live rows -> F (in-place in H region), tf32
            for (int j = tid; j < rows * CHN; j += NTHREADS) {
                const int r = j >> 4, c = j & 15;
                const int p = smi[OFF_IDX + base + r];
                const float* xt = &sm[OFF_XS + (c * 3 + st) * XS_ROW];
                const float* xm = &sm[OFF_XS + (c * 3 + sM) * XS_ROW];
                const float* xb = &sm[OFF_XS + (c * 3 + sb) * XS_ROW];
                float x00 = xt[p + 3], x01 = xt[p + 4], x02 = xt[p + 5];
                float x10 = xm[p + 3], x11 = xm[p + 4], x12 = xm[p + 5];
                float x20 = xb[p + 3], x21 = xb[p + 4], x22 = xb[p + 5];
                float gx = (x02 - x00) + 2.f * (x12 - x10) + (x22 - x20);
                float gy = (x20 - x00) + 2.f * (x21 - x01) + (x22 - x02);
                unsigned* dst = &smu[OFF_F + r * SF];
                dst[c]           = f2tf(x11);
                dst[CHN + c]     = f2tf(gx);
                dst[2 * CHN + c] = f2tf(gy);
            }
            // zero-pad F tail rows of the last active band
            for (int j = tid; j < (rows_pad - rows) * SF; j += NTHREADS)
                smu[OFF_F + rows * SF + j] = 0u;
            __syncthreads();

            const bool act12 = (rowBase < rows);

            // ---- layer 1: F[rows x 48] @ W1 -> H (in place over F) ----
            {
                float acc[2][4][4];
#pragma unroll
                for (int m = 0; m < 2; m++)
#pragma unroll
                    for (int n = 0; n < 4; n++)
#pragma unroll
                        for (int j = 0; j < 4; j++) acc[m][n][j] = 0.f;
                if (act12)
                    gemm_acc<6, SF, SF>(&smu[OFF_F], &smu[OFF_W1T], acc, rowBase, colBase, g, tq);
                __syncthreads();   // all reads of F done before overwrite
                if (act12)
                    epi_relu(acc, &sm[OFF_B1], &smu[OFF_H], rowBase, colBase, g, tq);
            }
            __syncthreads();

            // ---- layer 2: H @ W2 -> H (in place) ----
            {
                float acc[2][4][4];
#pragma unroll
                for (int m = 0; m < 2; m++)
#pragma unroll
                    for (int n = 0; n < 4; n++)
#pragma unroll
                        for (int j = 0; j < 4; j++) acc[m][n][j] = 0.f;
                if (act12)
                    gemm_acc<16, SW, SW>(&smu[OFF_H], &smu[OFF_W2T], acc, rowBase, colBase, g, tq);
                __syncthreads();
                if (act12)
                    epi_relu(acc, &sm[OFF_B2], &smu[OFF_H], rowBase, colBase, g, tq);
            }
            __syncthreads();

            // ---- layer 3: H @ W3[->16] -> scatter to out ----
            if (rowBase3 < rows) {
                float acc[4] = {0.f, 0.f, 0.f, 0.f};
#pragma unroll
                for (int kt = 0; kt < 16; kt++) {
                    const int k0 = kt * 8;
                    unsigned a0 = smu[OFF_H + (rowBase3 + g)     * SW + k0 + tq];
                    unsigned a1 = smu[OFF_H + (rowBase3 + g + 8) * SW + k0 + tq];
                    unsigned a2 = smu[OFF_H + (rowBase3 + g)     * SW + k0 + tq + 4];
                    unsigned a3 = smu[OFF_H + (rowBase3 + g + 8) * SW + k0 + tq + 4];
                    unsigned b0 = smu[OFF_W3T + (n03 + g) * SW + k0 + tq];
                    unsigned b1 = smu[OFF_W3T + (n03 + g) * SW + k0 + tq + 4];
                    mma_tf32(acc, a0, a1, a2, a3, b0, b1);
                }
                const int c0 = n03 + 2 * tq;
                const int i0 = rowBase3 + g;
                const int i1 = i0 + 8;
                const float bb0 = sm[OFF_B3 + c0], bb1 = sm[OFF_B3 + c0 + 1];
                if (i0 < rows) {
                    const int p = smi[OFF_IDX + base + i0];
                    out[((b * CHN + c0)     * HGT + y) * WID + p] = acc[0] + bb0;
                    out[((b * CHN + c0 + 1) * HGT + y) * WID + p] = acc[1] + bb1;
                }
                if (i1 < rows) {
                    const int p = smi[OFF_IDX + base + i1];
                    out[((b * CHN + c0)     * HGT + y) * WID + p] = acc[2] + bb0;
                    out[((b * CHN + c0 + 1) * HGT + y) * WID + p] = acc[3] + bb1;
                }
            }
            __syncthreads();   // H/F reuse next chunk
        }
        __syncthreads();       // XS slots / LIVE / IDX reuse next pool
    }
}

// ---------------- launch ----------------
extern "C" void kernel_launch(void* const* d_in, const int* in_sizes, int n_in,
                              void* d_out, int out_size) {
    const float* x  = (const float*)d_in[0];
    const float* fm = (const float*)d_in[1];
    const float* w1 = (const float*)d_in[2];
    const float* b1 = (const float*)d_in[3];
    const float* w2 = (const float*)d_in[4];
    const float* b2 = (const float*)d_in[5];
    const float* w3 = (const float*)d_in[6];
    const float* b3 = (const float*)d_in[7];
    float* out = (float*)d_out;

    (void)in_sizes; (void)n_in; (void)out_size;

    int dev = 0;
    cudaGetDevice(&dev);
    int sms = 148;
    cudaDeviceGetAttribute(&sms, cudaDevAttrMultiProcessorCount, dev);

    cudaFuncSetAttribute(nca_kernel, cudaFuncAttributeMaxDynamicSharedMemorySize, SMEM_BYTES);
    nca_kernel<<<sms, NTHREADS, SMEM_BYTES>>>(x, fm, w1, b1, w2, b2, w3, b3, out);
}

// round 11
// speedup vs baseline: 2.6265x; 1.1571x over previous
#include <cuda_runtime.h>

// ---------------- problem constants ----------------
#define CHN   16
#define EMB   128
#define HGT   256
#define WID   256
#define BATCH 16
#define POOLW 256
#define NPOOL (BATCH * HGT)   // 4096
#define NTHREADS 512

// ---------------- vec layouts ----------------
// Weights: float2 per (outRow, kt, tq) = {W[8kt+tq][n], W[8kt+tq+4][n]}, row stride
// in float2 units ≡ 4 (mod 16) -> per-half-warp phases hit 16 distinct bank-pairs.
#define S1 36                 // W1 rows (KT=6 -> min 24)
#define S2 68                 // W2/W3 rows (KT=16 -> min 64)
// Activations: float4 per (G, kt, lane) = {(r,k),(r+8,k),(r,k+4),(r+8,k+4)},
// r = 16G + (lane>>2), k = 8kt + (lane&3). Lane-consecutive -> conflict-free LDS.128.

#define OFF_W1V 0                               // 128*36 f2 = 9216 floats
#define OFF_W2V (OFF_W1V + 2 * 128 * S1)        // 9216
#define OFF_W3V (OFF_W2V + 2 * 128 * S2)        // 26624
#define OFF_B1  (OFF_W3V + 2 * 16 * S2)         // 28800
#define OFF_B2  (OFF_B1 + EMB)
#define OFF_B3  (OFF_B2 + EMB)
#define OFF_HV  (OFF_B3 + CHN)                  // 29072 (%4==0): H float4 region
#define HV_F4   (8 * 16 * 32)                   // 4096 float4 (F vec aliases low part)
#define XS_ROW  260
#define OFF_XS  (OFF_HV + 4 * HV_F4)            // 45456 (%4==0)
#define OFF_IDX (OFF_XS + CHN * 3 * XS_ROW + 4) // +12480+4 pad = 57940 (256 shorts)
#define OFF_CNT (OFF_IDX + 128)
#define OFF_NL  (OFF_CNT + 8)
#define SMEM_FLOATS (OFF_NL + 1)                // 58077
#define SMEM_BYTES  (SMEM_FLOATS * 4)           // 232308 <= 232448

// ---------------- helpers ----------------
__device__ __forceinline__ unsigned f2tf(float f) {
    unsigned r;
    asm("cvt.rna.tf32.f32 %0, %1;" : "=r"(r) : "f"(f));
    return r;
}

__device__ __forceinline__ void cp16(float* dst, const float* src) {
    unsigned d = (unsigned)__cvta_generic_to_shared(dst);
    asm volatile("cp.async.cg.shared.global [%0], [%1], 16;\n" :: "r"(d), "l"(src));
}

__device__ __forceinline__ void mma_tf32(float* d,
                                         unsigned a0, unsigned a1, unsigned a2, unsigned a3,
                                         unsigned b0, unsigned b1) {
    asm volatile(
        "mma.sync.aligned.m16n8k8.row.col.f32.tf32.tf32.f32 "
        "{%0,%1,%2,%3}, {%4,%5,%6,%7}, {%8,%9}, {%0,%1,%2,%3};\n"
        : "+f"(d[0]), "+f"(d[1]), "+f"(d[2]), "+f"(d[3])
        : "r"(a0), "r"(a1), "r"(a2), "r"(a3), "r"(b0), "r"(b1));
}

// 32x32 warp-tile accumulate from vec layouts. Av indexed at G=0; Bv float2 rows.
template <int KT, int BS>
__device__ __forceinline__ void gemm_vec(const uint4* __restrict__ Av,
                                         const uint2* __restrict__ Bv,
                                         float acc[2][4][4],
                                         int G0, int colBase, int g, int tq, int lane) {
#pragma unroll
    for (int kt = 0; kt < KT; kt++) {
        uint4 a0 = Av[(G0 * KT + kt) * 32 + lane];
        uint4 a1 = Av[((G0 + 1) * KT + kt) * 32 + lane];
#pragma unroll
        for (int n = 0; n < 4; n++) {
            uint2 b = Bv[(colBase + 8 * n + g) * BS + kt * 4 + tq];
            mma_tf32(acc[0][n], a0.x, a0.y, a0.z, a0.w, b.x, b.y);
            mma_tf32(acc[1][n], a1.x, a1.y, a1.z, a1.w, b.x, b.y);
        }
    }
}

// bias+relu, store 32x32 tile back into H vec layout (16-kt stride), tf32 bits
__device__ __forceinline__ void epi_vec(float acc[2][4][4], const float* __restrict__ bias,
                                        unsigned* __restrict__ Hv,
                                        int G0, int colBase, int g, int tq) {
    const int half = tq >> 1;
    const int te   = (2 * tq) & 3;
#pragma unroll
    for (int m = 0; m < 2; m++) {
        const int G = G0 + m;
#pragma unroll
        for (int n = 0; n < 4; n++) {
            const int ktp = (colBase >> 3) + n;
            const int c0  = colBase + 8 * n + 2 * tq;
            const float b0 = bias[c0], b1 = bias[c0 + 1];
            unsigned* pe = Hv + (((G * 16 + ktp) * 32 + g * 4 + te)     ) * 4 + half * 2;
            unsigned* po = Hv + (((G * 16 + ktp) * 32 + g * 4 + te + 1) ) * 4 + half * 2;
            *(uint2*)pe = make_uint2(f2tf(fmaxf(acc[m][n][0] + b0, 0.f)),
                                     f2tf(fmaxf(acc[m][n][2] + b0, 0.f)));
            *(uint2*)po = make_uint2(f2tf(fmaxf(acc[m][n][1] + b1, 0.f)),
                                     f2tf(fmaxf(acc[m][n][3] + b1, 0.f)));
        }
    }
}

// ---------------- kernel ----------------
__global__ void __launch_bounds__(NTHREADS, 1)
nca_kernel(const float* __restrict__ x,  const float* __restrict__ fm,
           const float* __restrict__ w1, const float* __restrict__ b1,
           const float* __restrict__ w2, const float* __restrict__ b2,
           const float* __restrict__ w3, const float* __restrict__ b3,
           float* __restrict__ out) {
    extern __shared__ float sm[];
    unsigned* smu   = reinterpret_cast<unsigned*>(sm);
    int*      smi   = reinterpret_cast<int*>(sm);
    short*    idx16 = reinterpret_cast<short*>(&sm[OFF_IDX]);
    uint4*    Hv4   = reinterpret_cast<uint4*>(&sm[OFF_HV]);
    unsigned* Hvu   = &smu[OFF_HV];
    const uint2* W1v = reinterpret_cast<const uint2*>(&sm[OFF_W1V]);
    const uint2* W2v = reinterpret_cast<const uint2*>(&sm[OFF_W2V]);
    const uint2* W3v = reinterpret_cast<const uint2*>(&sm[OFF_W3V]);

    const int tid  = threadIdx.x;
    const int lane = tid & 31;
    const int wid  = tid >> 5;
    const int g    = lane >> 2;
    const int tq   = lane & 3;
    const int rowBase  = (wid & 3) * 32;      // L1/L2: 4 warps over M
    const int colBase  = (wid >> 2) * 32;     //        4 warps over N
    const int G0       = rowBase >> 4;
    const int rowBase3 = (wid & 7) * 16;      // L3: 8 over M x 2 over N
    const int G3       = rowBase3 >> 4;
    const int n03      = (wid >> 3) * 8;

    // ---- stage weights into vec layouts (once) ----
    for (int i = tid; i < 128 * 24; i += NTHREADS) {           // W1: n x (6kt x 4tq)
        const int n = i / 24, j = i - n * 24, kt = j >> 2, t = j & 3;
        const int k = 8 * kt + t;
        smu[OFF_W1V + 2 * (n * S1 + kt * 4 + t)]     = f2tf(w1[k * EMB + n]);
        smu[OFF_W1V + 2 * (n * S1 + kt * 4 + t) + 1] = f2tf(w1[(k + 4) * EMB + n]);
    }
    for (int i = tid; i < 128 * 64; i += NTHREADS) {           // W2
        const int n = i >> 6, j = i & 63, kt = j >> 2, t = j & 3;
        const int k = 8 * kt + t;
        smu[OFF_W2V + 2 * (n * S2 + kt * 4 + t)]     = f2tf(w2[k * EMB + n]);
        smu[OFF_W2V + 2 * (n * S2 + kt * 4 + t) + 1] = f2tf(w2[(k + 4) * EMB + n]);
    }
    for (int i = tid; i < 16 * 64; i += NTHREADS) {            // W3
        const int n = i >> 6, j = i & 63, kt = j >> 2, t = j & 3;
        const int k = 8 * kt + t;
        smu[OFF_W3V + 2 * (n * S2 + kt * 4 + t)]     = f2tf(w3[k * CHN + n]);
        smu[OFF_W3V + 2 * (n * S2 + kt * 4 + t) + 1] = f2tf(w3[(k + 4) * CHN + n]);
    }
    for (int i = tid; i < EMB; i += NTHREADS) {
        sm[OFF_B1 + i] = b1[i];
        sm[OFF_B2 + i] = b2[i];
    }
    if (tid < CHN) sm[OFF_B3 + tid] = b3[tid];
    // zero left-pad words (+0..+3) of all 48 XS rows, plus the 4 tail-pad floats
    for (int i = tid; i < 49 * 4; i += NTHREADS)
        sm[OFF_XS + (i >> 2) * XS_ROW + (i & 3)] = 0.f;
    __syncthreads();

    // ---- strip of contiguous pools for this CTA ----
    const int per = (NPOOL + gridDim.x - 1) / gridDim.x;
    const int t0  = blockIdx.x * per;
    const int t1  = min(t0 + per, NPOOL);

    for (int t = t0; t < t1; t++) {
        const int b = t >> 8;
        const int y = t & 255;

        // ---- staging: full reload at strip/image start, else prefetch was issued ----
        if (t == t0 || y == 0) {
            for (int j = y - 1; j <= y + 1; j++) {
                const int slot = ((j % 3) + 3) % 3;
                if (j < 0 || j >= HGT) {
                    for (int i = tid; i < CHN * 256; i += NTHREADS)
                        sm[OFF_XS + ((i >> 8) * 3 + slot) * XS_ROW + 4 + (i & 255)] = 0.f;
                } else {
                    for (int i = tid; i < CHN * 64; i += NTHREADS) {
                        const int c = i >> 6, q = i & 63;
                        cp16(&sm[OFF_XS + (c * 3 + slot) * XS_ROW + 4 + 4 * q],
                             &x[((b * CHN + c) * HGT + j) * WID + 4 * q]);
                    }
                }
            }
            asm volatile("cp.async.commit_group;\n");
        }
        asm volatile("cp.async.wait_group 0;\n" ::: "memory");
        __syncthreads();

        const int st = (y + 2) % 3;   // slot of row y-1
        const int sM = y % 3;
        const int sb = (y + 1) % 3;

        // ---- sel + ballot compaction ----
        unsigned bal = 0;
        int live = 0;
        if (tid < POOLW) {
            const int p = tid;
            const float* at = &sm[OFF_XS + (3 * 3 + st) * XS_ROW];
            const float* am = &sm[OFF_XS + (3 * 3 + sM) * XS_ROW];
            const float* ab = &sm[OFF_XS + (3 * 3 + sb) * XS_ROW];
            float m = at[p + 3];
            m = fmaxf(m, at[p + 4]); m = fmaxf(m, at[p + 5]);
            m = fmaxf(m, am[p + 3]); m = fmaxf(m, am[p + 4]); m = fmaxf(m, am[p + 5]);
            m = fmaxf(m, ab[p + 3]); m = fmaxf(m, ab[p + 4]); m = fmaxf(m, ab[p + 5]);
            float fire = fm[(b * HGT + y) * WID + p];
            live = (m > 0.1f && fire != 0.f) ? 1 : 0;
            bal = __ballot_sync(0xffffffffu, live);
            if (lane == 0) smi[OFF_CNT + wid] = __popc(bal);
        }
        // zero the whole output row (live pixels overwritten after barriers)
        for (int i = tid; i < 1024; i += NTHREADS) {
            const int c = i >> 6, q = i & 63;
            *(float4*)&out[((b * CHN + c) * HGT + y) * WID + 4 * q] =
                make_float4(0.f, 0.f, 0.f, 0.f);
        }
        __syncthreads();
        if (tid == 0) {
            int s = 0;
#pragma unroll
            for (int w_ = 0; w_ < 8; w_++) {
                int c = smi[OFF_CNT + w_];
                smi[OFF_CNT + w_] = s;
                s += c;
            }
            smi[OFF_NL] = s;
        }
        __syncthreads();
        if (tid < POOLW && live)
            idx16[smi[OFF_CNT + wid] + __popc(bal & ((1u << lane) - 1))] = (short)tid;
        __syncthreads();
        const int NL = smi[OFF_NL];
        const bool doPrefetch = (t + 1 < t1) && (y < 255);
        bool prefetched = false;

        // ---- prefetch helper body used at two sites ----
        #define ISSUE_PREFETCH() do {                                                    \
            const int j = y + 2, slot = j % 3;                                           \
            if (j < HGT) {                                                               \
                for (int i = tid; i < CHN * 64; i += NTHREADS) {                         \
                    const int c = i >> 6, q = i & 63;                                    \
                    cp16(&sm[OFF_XS + (c * 3 + slot) * XS_ROW + 4 + 4 * q],              \
                         &x[((b * CHN + c) * HGT + j) * WID + 4 * q]);                   \
                }                                                                        \
                asm volatile("cp.async.commit_group;\n");                                \
            } else {                                                                     \
                for (int i = tid; i < CHN * 256; i += NTHREADS)                          \
                    sm[OFF_XS + ((i >> 8) * 3 + slot) * XS_ROW + 4 + (i & 255)] = 0.f;   \
            }                                                                            \
        } while (0)

        if (NL == 0) {
            if (doPrefetch) ISSUE_PREFETCH();
            __syncthreads();
            continue;
        }

        // ---- compacted GEMM chunks of up to 128 rows ----
        for (int base = 0; base < NL; base += 128) {
            const int rows = min(128, NL - base);
            const int rows_pad = (rows + 31) & ~31;
            const int Gcnt = rows_pad >> 4;

            // features -> F vec (aliases low Hv region), KT=6 layout
            for (int i = tid; i < Gcnt * 128; i += NTHREADS) {
                const int G = i >> 7, r2 = i & 127, gg = r2 >> 4, c = r2 & 15;
                const float* xt = &sm[OFF_XS + (c * 3 + st) * XS_ROW];
                const float* xm = &sm[OFF_XS + (c * 3 + sM) * XS_ROW];
                const float* xb = &sm[OFF_XS + (c * 3 + sb) * XS_ROW];
                float xv[2] = {0.f, 0.f}, gx[2] = {0.f, 0.f}, gy[2] = {0.f, 0.f};
#pragma unroll
                for (int h = 0; h < 2; h++) {
                    const int r = 16 * G + 8 * h + gg;
                    if (r < rows) {
                        const int p = idx16[base + r];
                        float x00 = xt[p + 3], x01 = xt[p + 4], x02 = xt[p + 5];
                        float x10 = xm[p + 3], x11 = xm[p + 4], x12 = xm[p + 5];
                        float x20 = xb[p + 3], x21 = xb[p + 4], x22 = xb[p + 5];
                        xv[h] = x11;
                        gx[h] = (x02 - x00) + 2.f * (x12 - x10) + (x22 - x20);
                        gy[h] = (x20 - x00) + 2.f * (x21 - x01) + (x22 - x02);
                    }
                }
                const int ktb = c >> 3, tr = c & 3, hf = (c >> 2) & 1;
                unsigned* q0 = Hvu + (((G * 6 + ktb)     * 32 + gg * 4 + tr)) * 4 + hf * 2;
                unsigned* q1 = Hvu + (((G * 6 + 2 + ktb) * 32 + gg * 4 + tr)) * 4 + hf * 2;
                unsigned* q2 = Hvu + (((G * 6 + 4 + ktb) * 32 + gg * 4 + tr)) * 4 + hf * 2;
                *(uint2*)q0 = make_uint2(f2tf(xv[0]), f2tf(xv[1]));
                *(uint2*)q1 = make_uint2(f2tf(gx[0]), f2tf(gx[1]));
                *(uint2*)q2 = make_uint2(f2tf(gy[0]), f2tf(gy[1]));
            }
            __syncthreads();

            // prefetch next pool's row once last chunk's features are built
            if (doPrefetch && !prefetched && base + 128 >= NL) {
                ISSUE_PREFETCH();
                prefetched = true;
            }

            const bool act12 = (rowBase < rows);

            // ---- layer 1: Fvec @ W1v -> Hvec (in place) ----
            {
                float acc[2][4][4];
#pragma unroll
                for (int m = 0; m < 2; m++)
#pragma unroll
                    for (int n = 0; n < 4; n++)
#pragma unroll
                        for (int j = 0; j < 4; j++) acc[m][n][j] = 0.f;
                if (act12)
                    gemm_vec<6, S1>(Hv4, W1v, acc, G0, colBase, g, tq, lane);
                __syncthreads();
                if (act12)
                    epi_vec(acc, &sm[OFF_B1], Hvu, G0, colBase, g, tq);
            }
            __syncthreads();

            // ---- layer 2: Hvec @ W2v -> Hvec (in place) ----
            {
                float acc[2][4][4];
#pragma unroll
                for (int m = 0; m < 2; m++)
#pragma unroll
                    for (int n = 0; n < 4; n++)
#pragma unroll
                        for (int j = 0; j < 4; j++) acc[m][n][j] = 0.f;
                if (act12)
                    gemm_vec<16, S2>(Hv4, W2v, acc, G0, colBase, g, tq, lane);
                __syncthreads();
                if (act12)
                    epi_vec(acc, &sm[OFF_B2], Hvu, G0, colBase, g, tq);
            }
            __syncthreads();

            // ---- layer 3: Hvec @ W3v -> scatter ----
            if (rowBase3 < rows) {
                float acc[4] = {0.f, 0.f, 0.f, 0.f};
#pragma unroll
                for (int kt = 0; kt < 16; kt++) {
                    uint4 a = Hv4[(G3 * 16 + kt) * 32 + lane];
                    uint2 bb = W3v[(n03 + g) * S2 + kt * 4 + tq];
                    mma_tf32(acc, a.x, a.y, a.z, a.w, bb.x, bb.y);
                }
                const int c0 = n03 + 2 * tq;
                const int i0 = rowBase3 + g;
                const int i1 = i0 + 8;
                const float bb0 = sm[OFF_B3 + c0], bb1 = sm[OFF_B3 + c0 + 1];
                if (i0 < rows) {
                    const int p = idx16[base + i0];
                    out[((b * CHN + c0)     * HGT + y) * WID + p] = acc[0] + bb0;
                    out[((b * CHN + c0 + 1) * HGT + y) * WID + p] = acc[1] + bb1;
                }
                if (i1 < rows) {
                    const int p = idx16[base + i1];
                    out[((b * CHN + c0)     * HGT + y) * WID + p] = acc[2] + bb0;
                    out[((b * CHN + c0 + 1) * HGT + y) * WID + p] = acc[3] + bb1;
                }
            }
            __syncthreads();   // Hvec/Fvec reuse next chunk
        }
        #undef ISSUE_PREFETCH
    }
}

// ---------------- launch ----------------
extern "C" void kernel_launch(void* const* d_in, const int* in_sizes, int n_in,
                              void* d_out, int out_size) {
    const float* x  = (const float*)d_in[0];
    const float* fm = (const float*)d_in[1];
    const float* w1 = (const float*)d_in[2];
    const float* b1 = (const float*)d_in[3];
    const float* w2 = (const float*)d_in[4];
    const float* b2 = (const float*)d_in[5];
    const float* w3 = (const float*)d_in[6];
    const float* b3 = (const float*)d_in[7];
    float* out = (float*)d_out;

    (void)in_sizes; (void)n_in; (void)out_size;

    int dev = 0;
    cudaGetDevice(&dev);
    int sms = 148;
    cudaDeviceGetAttribute(&sms, cudaDevAttrMultiProcessorCount, dev);

    cudaFuncSetAttribute(nca_kernel, cudaFuncAttributeMaxDynamicSharedMemorySize, SMEM_BYTES);
    nca_kernel<<<sms, NTHREADS, SMEM_BYTES>>>(x, fm, w1, b1, w2, b2, w3, b3, out);
}

// round 15
// speedup vs baseline: 3.3965x; 1.2932x over previous
#include <cuda_runtime.h>
#include <cuda_fp16.h>

// ---------------- problem constants ----------------
#define CHN   16
#define EMB   128
#define HGT   256
#define WID   256
#define BATCH 16
#define POOLW 256
#define NPOOL (BATCH * HGT)   // 4096
#define NTHREADS 512

// ---------------- layouts ----------------
// Weights: uint2 per (outRow n, kt16, tq) = {h2(W[k][n],W[k+1][n]), h2(W[k+8][n],W[k+9][n])},
// k = 16*kt + 2*tq. Row stride (uint2 units) ≡ 4 mod 16 -> conflict-free LDS.64.
#define S1H 20                // W1: 3 kt-steps (K=48), min 12
#define S2H 36                // W2/W3: 8 kt-steps (K=128), min 32
// Activations: uint4 per (G, kt16, lane=4*gg+tq) =
//   {(r,pair 8kt+tq), (r,pair 8kt+tq+4), (r+8,pair 8kt+tq), (r+8,pair 8kt+tq+4)}
// r = 16G+gg; each 32-bit = half2 of adjacent k. A-load: LDS.128, use (x,z,y,w).

#define OFF_W1V 0                              // 2*128*20 = 5120 floats
#define OFF_W2V (OFF_W1V + 2 * 128 * S1H)      // 5120
#define OFF_W3V (OFF_W2V + 2 * 128 * S2H)      // 14336
#define OFF_B1  (OFF_W3V + 2 * 16 * S2H)       // 15488
#define OFF_B2  (OFF_B1 + EMB)
#define OFF_B3  (OFF_B2 + EMB)
#define OFF_HV  (OFF_B3 + CHN)                 // 15760 (x4 bytes %16==0)
#define HV_ELEMS (8 * 8 * 32)                  // 2048 uint4 (F KT=3 aliases low part)
#define XS_ROW  264
#define OFF_XS  (OFF_HV + 4 * HV_ELEMS)        // 23952
#define OFF_IDX (OFF_XS + CHN * 3 * XS_ROW)    // 36624 (256 shorts)
#define OFF_CNT (OFF_IDX + 128)
#define OFF_NL  (OFF_CNT + 8)
#define SMEM_FLOATS (OFF_NL + 1)
#define SMEM_BYTES  (SMEM_FLOATS * 4)          // ~147 KB

// ---------------- helpers ----------------
__device__ __forceinline__ unsigned h2pack(float lo, float hi) {
    unsigned r;
    asm("cvt.rn.f16x2.f32 %0, %1, %2;" : "=r"(r) : "f"(hi), "f"(lo));
    return r;
}

__device__ __forceinline__ void cp16(float* dst, const float* src) {
    unsigned d = (unsigned)__cvta_generic_to_shared(dst);
    asm volatile("cp.async.cg.shared.global [%0], [%1], 16;\n" :: "r"(d), "l"(src));
}

__device__ __forceinline__ void mma_f16(float* d,
                                        unsigned a0, unsigned a1, unsigned a2, unsigned a3,
                                        unsigned b0, unsigned b1) {
    asm volatile(
        "mma.sync.aligned.m16n8k16.row.col.f32.f16.f16.f32 "
        "{%0,%1,%2,%3}, {%4,%5,%6,%7}, {%8,%9}, {%0,%1,%2,%3};\n"
        : "+f"(d[0]), "+f"(d[1]), "+f"(d[2]), "+f"(d[3])
        : "r"(a0), "r"(a1), "r"(a2), "r"(a3), "r"(b0), "r"(b1));
}

// 32x32 warp-tile accumulate. Av: activation fragment elements; Bv: weight uint2 rows.
template <int KT, int BS>
__device__ __forceinline__ void gemm_f16(const uint4* __restrict__ Av,
                                         const uint2* __restrict__ Bv,
                                         float acc[2][4][4],
                                         int G0, int colBase, int g, int tq, int lane) {
#pragma unroll
    for (int kt = 0; kt < KT; kt++) {
        uint4 v0 = Av[(G0 * KT + kt) * 32 + lane];
        uint4 v1 = Av[((G0 + 1) * KT + kt) * 32 + lane];
#pragma unroll
        for (int n = 0; n < 4; n++) {
            uint2 b = Bv[(colBase + 8 * n + g) * BS + kt * 4 + tq];
            mma_f16(acc[0][n], v0.x, v0.z, v0.y, v0.w, b.x, b.y);
            mma_f16(acc[1][n], v1.x, v1.z, v1.y, v1.w, b.x, b.y);
        }
    }
}

// bias+relu -> f16 fragment store (KT=8 output layout), 4 conflict-free STS.128
__device__ __forceinline__ void epi_f16(float acc[2][4][4], const float* __restrict__ bias,
                                        uint4* __restrict__ Hv,
                                        int G0, int colBase, int g, int tq, int W) {
#pragma unroll
    for (int m = 0; m < 2; m++) {
#pragma unroll
        for (int j = 0; j < 2; j++) {
            const int cl = colBase + 16 * j + 2 * tq;   // n=2j   columns
            const int ch = cl + 8;                      // n=2j+1 columns
            const float bl0 = bias[cl], bl1 = bias[cl + 1];
            const float bh0 = bias[ch], bh1 = bias[ch + 1];
            uint4 v;
            v.x = h2pack(fmaxf(acc[m][2*j][0]   + bl0, 0.f), fmaxf(acc[m][2*j][1]   + bl1, 0.f));
            v.y = h2pack(fmaxf(acc[m][2*j+1][0] + bh0, 0.f), fmaxf(acc[m][2*j+1][1] + bh1, 0.f));
            v.z = h2pack(fmaxf(acc[m][2*j][2]   + bl0, 0.f), fmaxf(acc[m][2*j][3]   + bl1, 0.f));
            v.w = h2pack(fmaxf(acc[m][2*j+1][2] + bh0, 0.f), fmaxf(acc[m][2*j+1][3] + bh1, 0.f));
            Hv[((G0 + m) * 8 + 2 * W + j) * 32 + 4 * g + tq] = v;
        }
    }
}

// ---------------- kernel ----------------
__global__ void __launch_bounds__(NTHREADS, 1)
nca_kernel(const float* __restrict__ x,  const float* __restrict__ fm,
           const float* __restrict__ w1, const float* __restrict__ b1,
           const float* __restrict__ w2, const float* __restrict__ b2,
           const float* __restrict__ w3, const float* __restrict__ b3,
           float* __restrict__ out) {
    extern __shared__ float sm[];
    int*   smi   = reinterpret_cast<int*>(sm);
    short* idx16 = reinterpret_cast<short*>(&sm[OFF_IDX]);
    char*  smb   = reinterpret_cast<char*>(sm);
    uint4* Hv4   = reinterpret_cast<uint4*>(&sm[OFF_HV]);
    const uint2* W1v = reinterpret_cast<const uint2*>(&sm[OFF_W1V]);
    const uint2* W2v = reinterpret_cast<const uint2*>(&sm[OFF_W2V]);
    const uint2* W3v = reinterpret_cast<const uint2*>(&sm[OFF_W3V]);

    const int tid  = threadIdx.x;
    const int lane = tid & 31;
    const int wid  = tid >> 5;
    const int g    = lane >> 2;
    const int tq   = lane & 3;
    const int W    = wid >> 2;                // column-block id (L1/L2)
    const int rowBase  = (wid & 3) * 32;
    const int colBase  = W * 32;
    const int G0       = rowBase >> 4;
    const int rowBase3 = (wid & 7) * 16;      // L3: 8 over M x 2 over N
    const int G3       = wid & 7;
    const int n03      = (wid >> 3) * 8;

    // ---- stage weights into f16 fragment layouts (once) ----
    for (int i = tid; i < 128 * 12; i += NTHREADS) {           // W1: 3kt x 4tq
        const int n = i / 12, j = i - n * 12, kt = j >> 2, tq2 = j & 3;
        const int k = 16 * kt + 2 * tq2;
        unsigned lo = h2pack(w1[k * EMB + n],       w1[(k + 1) * EMB + n]);
        unsigned hi = h2pack(w1[(k + 8) * EMB + n], w1[(k + 9) * EMB + n]);
        *(uint2*)&sm[OFF_W1V + 2 * (n * S1H + kt * 4 + tq2)] = make_uint2(lo, hi);
    }
    for (int i = tid; i < 128 * 32; i += NTHREADS) {           // W2: 8kt x 4tq
        const int n = i >> 5, j = i & 31, kt = j >> 2, tq2 = j & 3;
        const int k = 16 * kt + 2 * tq2;
        unsigned lo = h2pack(w2[k * EMB + n],       w2[(k + 1) * EMB + n]);
        unsigned hi = h2pack(w2[(k + 8) * EMB + n], w2[(k + 9) * EMB + n]);
        *(uint2*)&sm[OFF_W2V + 2 * (n * S2H + kt * 4 + tq2)] = make_uint2(lo, hi);
    }
    for (int i = tid; i < 16 * 32; i += NTHREADS) {            // W3
        const int n = i >> 5, j = i & 31, kt = j >> 2, tq2 = j & 3;
        const int k = 16 * kt + 2 * tq2;
        unsigned lo = h2pack(w3[k * CHN + n],       w3[(k + 1) * CHN + n]);
        unsigned hi = h2pack(w3[(k + 8) * CHN + n], w3[(k + 9) * CHN + n]);
        *(uint2*)&sm[OFF_W3V + 2 * (n * S2H + kt * 4 + tq2)] = make_uint2(lo, hi);
    }
    for (int i = tid; i < EMB; i += NTHREADS) {
        sm[OFF_B1 + i] = b1[i];
        sm[OFF_B2 + i] = b2[i];
    }
    if (tid < CHN) sm[OFF_B3 + tid] = b3[tid];
    // zero left pad (+0..+3) and right halo (+260..+263) of all 48 XS rows
    for (int i = tid; i < 48 * 8; i += NTHREADS) {
        const int rr = i >> 3, j = i & 7;
        sm[OFF_XS + rr * XS_ROW + (j < 4 ? j : 256 + j)] = 0.f;
    }
    __syncthreads();

    // ---- strip of contiguous pools for this CTA ----
    const int per = (NPOOL + gridDim.x - 1) / gridDim.x;
    const int t0  = blockIdx.x * per;
    const int t1  = min(t0 + per, NPOOL);

    for (int t = t0; t < t1; t++) {
        const int b = t >> 8;
        const int y = t & 255;

        // ---- staging: full reload at strip/image start, else prefetch pending ----
        if (t == t0 || y == 0) {
            for (int j = y - 1; j <= y + 1; j++) {
                const int slot = ((j % 3) + 3) % 3;
                if (j < 0 || j >= HGT) {
                    for (int i = tid; i < CHN * 256; i += NTHREADS)
                        sm[OFF_XS + ((i >> 8) * 3 + slot) * XS_ROW + 4 + (i & 255)] = 0.f;
                } else {
                    for (int i = tid; i < CHN * 64; i += NTHREADS) {
                        const int c = i >> 6, q = i & 63;
                        cp16(&sm[OFF_XS + (c * 3 + slot) * XS_ROW + 4 + 4 * q],
                             &x[((b * CHN + c) * HGT + j) * WID + 4 * q]);
                    }
                }
            }
            asm volatile("cp.async.commit_group;\n");
        }
        asm volatile("cp.async.wait_group 0;\n" ::: "memory");
        __syncthreads();

        const int st = (y + 2) % 3;   // slot of row y-1
        const int sM = y % 3;
        const int sb = (y + 1) % 3;

        // ---- sel + ballot compaction ----
        unsigned bal = 0;
        int live = 0;
        if (tid < POOLW) {
            const int p = tid;
            const float* at = &sm[OFF_XS + (3 * 3 + st) * XS_ROW];
            const float* am = &sm[OFF_XS + (3 * 3 + sM) * XS_ROW];
            const float* ab = &sm[OFF_XS + (3 * 3 + sb) * XS_ROW];
            float m = at[p + 3];
            m = fmaxf(m, at[p + 4]); m = fmaxf(m, at[p + 5]);
            m = fmaxf(m, am[p + 3]); m = fmaxf(m, am[p + 4]); m = fmaxf(m, am[p + 5]);
            m = fmaxf(m, ab[p + 3]); m = fmaxf(m, ab[p + 4]); m = fmaxf(m, ab[p + 5]);
            float fire = fm[(b * HGT + y) * WID + p];
            live = (m > 0.1f && fire != 0.f) ? 1 : 0;
            bal = __ballot_sync(0xffffffffu, live);
            if (lane == 0) smi[OFF_CNT + wid] = __popc(bal);
        }
        // zero entire output row (live pixels overwritten later)
        for (int i = tid; i < 1024; i += NTHREADS) {
            const int c = i >> 6, q = i & 63;
            *(float4*)&out[((b * CHN + c) * HGT + y) * WID + 4 * q] =
                make_float4(0.f, 0.f, 0.f, 0.f);
        }
        __syncthreads();
        if (tid == 0) {
            int s = 0;
#pragma unroll
            for (int w_ = 0; w_ < 8; w_++) {
                int c = smi[OFF_CNT + w_];
                smi[OFF_CNT + w_] = s;
                s += c;
            }
            smi[OFF_NL] = s;
        }
        __syncthreads();
        if (tid < POOLW && live)
            idx16[smi[OFF_CNT + wid] + __popc(bal & ((1u << lane) - 1))] = (short)tid;
        __syncthreads();
        const int NL = smi[OFF_NL];
        const bool doPrefetch = (t + 1 < t1) && (y < 255);
        bool prefetched = false;

        #define ISSUE_PREFETCH() do {                                                    \
            const int j = y + 2, slot = j % 3;                                           \
            if (j < HGT) {                                                               \
                for (int i = tid; i < CHN * 64; i += NTHREADS) {                         \
                    const int c = i >> 6, q = i & 63;                                    \
                    cp16(&sm[OFF_XS + (c * 3 + slot) * XS_ROW + 4 + 4 * q],              \
                         &x[((b * CHN + c) * HGT + j) * WID + 4 * q]);                   \
                }                                                                        \
                asm volatile("cp.async.commit_group;\n");                                \
            } else {                                                                     \
                for (int i = tid; i < CHN * 256; i += NTHREADS)                          \
                    sm[OFF_XS + ((i >> 8) * 3 + slot) * XS_ROW + 4 + (i & 255)] = 0.f;   \
            }                                                                            \
        } while (0)

        if (NL == 0) {
            if (doPrefetch) ISSUE_PREFETCH();
            __syncthreads();
            continue;
        }

        // ---- compacted GEMM chunks of up to 128 rows ----
        for (int base = 0; base < NL; base += 128) {
            const int rows = min(128, NL - base);

            // features -> F fragment (KT=3 layout in Hv region), half2-packed
            for (int i = tid; i < rows * 8; i += NTHREADS) {
                const int r = i >> 3, cp = i & 7;
                const int p = idx16[base + r];
                float xv[2], gx[2], gy[2];
#pragma unroll
                for (int h = 0; h < 2; h++) {
                    const int c = 2 * cp + h;
                    const float* xt = &sm[OFF_XS + (c * 3 + st) * XS_ROW];
                    const float* xm = &sm[OFF_XS + (c * 3 + sM) * XS_ROW];
                    const float* xb = &sm[OFF_XS + (c * 3 + sb) * XS_ROW];
                    float x00 = xt[p + 3], x01 = xt[p + 4], x02 = xt[p + 5];
                    float x10 = xm[p + 3], x11 = xm[p + 4], x12 = xm[p + 5];
                    float x20 = xb[p + 3], x21 = xb[p + 4], x22 = xb[p + 5];
                    xv[h] = x11;
                    gx[h] = (x02 - x00) + 2.f * (x12 - x10) + (x22 - x20);
                    gy[h] = (x20 - x00) + 2.f * (x21 - x01) + (x22 - x02);
                }
                const int G = r >> 4, rr = r & 15, gg = rr & 7;
                const unsigned lanep = 4 * gg + (cp & 3);
                const unsigned sub = ((rr >> 3) << 3) + ((cp >> 2) << 2);
                const unsigned eb = (unsigned)(OFF_HV * 4)
                                  + ((G * 3) * 32 + lanep) * 16 + sub;
                *(unsigned*)(smb + eb)            = h2pack(xv[0], xv[1]);   // kt 0 (x)
                *(unsigned*)(smb + eb + 32 * 16)  = h2pack(gx[0], gx[1]);   // kt 1 (gx)
                *(unsigned*)(smb + eb + 64 * 16)  = h2pack(gy[0], gy[1]);   // kt 2 (gy)
            }
            __syncthreads();

            // prefetch next pool's row once last chunk's features are built
            if (doPrefetch && !prefetched && base + 128 >= NL) {
                ISSUE_PREFETCH();
                prefetched = true;
            }

            const bool act12 = (rowBase < rows);

            // ---- layer 1: F(KT=3) @ W1 -> H(KT=8, in place) ----
            {
                float acc[2][4][4];
#pragma unroll
                for (int m = 0; m < 2; m++)
#pragma unroll
                    for (int n = 0; n < 4; n++)
#pragma unroll
                        for (int j = 0; j < 4; j++) acc[m][n][j] = 0.f;
                if (act12)
                    gemm_f16<3, S1H>(Hv4, W1v, acc, G0, colBase, g, tq, lane);
                __syncthreads();   // all F reads done before overwrite
                if (act12)
                    epi_f16(acc, &sm[OFF_B1], Hv4, G0, colBase, g, tq, W);
            }
            __syncthreads();

            // ---- layer 2: H @ W2 -> H (in place) ----
            {
                float acc[2][4][4];
#pragma unroll
                for (int m = 0; m < 2; m++)
#pragma unroll
                    for (int n = 0; n < 4; n++)
#pragma unroll
                        for (int j = 0; j < 4; j++) acc[m][n][j] = 0.f;
                if (act12)
                    gemm_f16<8, S2H>(Hv4, W2v, acc, G0, colBase, g, tq, lane);
                __syncthreads();
                if (act12)
                    epi_f16(acc, &sm[OFF_B2], Hv4, G0, colBase, g, tq, W);
            }
            __syncthreads();

            // ---- layer 3: H @ W3[->16] -> scatter ----
            if (rowBase3 < rows) {
                float acc[4] = {0.f, 0.f, 0.f, 0.f};
#pragma unroll
                for (int kt = 0; kt < 8; kt++) {
                    uint4 v = Hv4[(G3 * 8 + kt) * 32 + lane];
                    uint2 bb = W3v[(n03 + g) * S2H + kt * 4 + tq];
                    mma_f16(acc, v.x, v.z, v.y, v.w, bb.x, bb.y);
                }
                const int c0 = n03 + 2 * tq;
                const int i0 = rowBase3 + g;
                const int i1 = i0 + 8;
                const float bb0 = sm[OFF_B3 + c0], bb1 = sm[OFF_B3 + c0 + 1];
                if (i0 < rows) {
                    const int p = idx16[base + i0];
                    out[((b * CHN + c0)     * HGT + y) * WID + p] = acc[0] + bb0;
                    out[((b * CHN + c0 + 1) * HGT + y) * WID + p] = acc[1] + bb1;
                }
                if (i1 < rows) {
                    const int p = idx16[base + i1];
                    out[((b * CHN + c0)     * HGT + y) * WID + p] = acc[2] + bb0;
                    out[((b * CHN + c0 + 1) * HGT + y) * WID + p] = acc[3] + bb1;
                }
            }
            __syncthreads();   // H/F reuse next chunk
        }
        #undef ISSUE_PREFETCH
    }
}

// ---------------- launch ----------------
extern "C" void kernel_launch(void* const* d_in, const int* in_sizes, int n_in,
                              void* d_out, int out_size) {
    const float* x  = (const float*)d_in[0];
    const float* fm = (const float*)d_in[1];
    const float* w1 = (const float*)d_in[2];
    const float* b1 = (const float*)d_in[3];
    const float* w2 = (const float*)d_in[4];
    const float* b2 = (const float*)d_in[5];
    const float* w3 = (const float*)d_in[6];
    const float* b3 = (const float*)d_in[7];
    float* out = (float*)d_out;

    (void)in_sizes; (void)n_in; (void)out_size;

    int dev = 0;
    cudaGetDevice(&dev);
    int sms = 148;
    cudaDeviceGetAttribute(&sms, cudaDevAttrMultiProcessorCount, dev);

    cudaFuncSetAttribute(nca_kernel, cudaFuncAttributeMaxDynamicSharedMemorySize, SMEM_BYTES);
    nca_kernel<<<sms, NTHREADS, SMEM_BYTES>>>(x, fm, w1, b1, w2, b2, w3, b3, out);
}

// round 16
// speedup vs baseline: 3.6723x; 1.0812x over previous
#include <cuda_runtime.h>
#include <cuda_fp16.h>

// ---------------- problem constants ----------------
#define CHN   16
#define EMB   128
#define HGT   256
#define WID   256
#define BATCH 16
#define POOLW 256
#define NPOOL (BATCH * HGT)   // 4096
#define NTHREADS 512

// ---------------- layouts ----------------
// Weights: uint2 per (n, kt16, tq) = {h2(W[k][n],W[k+1][n]), h2(W[k+8][n],W[k+9][n])},
// k = 16*kt + 2*tq. Row stride (uint2 units) ≡ 4 or 12 (mod 16) -> conflict-free LDS.64.
#define S1H 12                // W1: 3 kt-steps (K=48); 12 ≡ 12 mod 16
#define S2H 36                // W2/W3: 8 kt-steps (K=128); 36 ≡ 4 mod 16
// Activations: uint4 per (G, kt16, lane=4*gg+tq): see epi/gemm fragment mapping.

#define OFF_W1V 0                         // 2*128*12 = 3072 floats
#define OFF_W2V 3072                      // 2*128*36 = 9216
#define OFF_W3V 12288                     // 2*16*36  = 1152
#define OFF_B1  13440
#define OFF_B2  13568
#define OFF_B3  13696
#define OFF_G   13712                     // two per-group regions follow
// per-group offsets (floats, relative to group base):
#define G_HV    0                         // 2048 uint4 = 8192 floats (F KT=3 aliases low part)
#define XS_ROW  264
#define G_XS    8192                      // 16ch x 3 slots x 264 = 12672
#define G_IDX   20864                     // 256 shorts = 128 floats
#define G_CNT   20992                     // 8 ints
#define G_NL    21000
#define GSTRIDE 21008                     // 16B-aligned
#define SMEM_FLOATS (OFF_G + 2 * GSTRIDE) // 55728
#define SMEM_BYTES  (SMEM_FLOATS * 4)     // 222,912 B

// ---------------- helpers ----------------
__device__ __forceinline__ unsigned h2pack(float lo, float hi) {
    unsigned r;
    asm("cvt.rn.f16x2.f32 %0, %1, %2;" : "=r"(r) : "f"(hi), "f"(lo));
    return r;
}

__device__ __forceinline__ void cp16(float* dst, const float* src) {
    unsigned d = (unsigned)__cvta_generic_to_shared(dst);
    asm volatile("cp.async.cg.shared.global [%0], [%1], 16;\n" :: "r"(d), "l"(src));
}

__device__ __forceinline__ void mma_f16(float* d,
                                        unsigned a0, unsigned a1, unsigned a2, unsigned a3,
                                        unsigned b0, unsigned b1) {
    asm volatile(
        "mma.sync.aligned.m16n8k16.row.col.f32.f16.f16.f32 "
        "{%0,%1,%2,%3}, {%4,%5,%6,%7}, {%8,%9}, {%0,%1,%2,%3};\n"
        : "+f"(d[0]), "+f"(d[1]), "+f"(d[2]), "+f"(d[3])
        : "r"(a0), "r"(a1), "r"(a2), "r"(a3), "r"(b0), "r"(b1));
}

// group barrier: id 1 or 2, 256 threads
#define GBAR() asm volatile("bar.sync %0, 256;" :: "r"(gbar_id) : "memory")

// 32x32 warp-tile accumulate (one colBase), fragment layouts as in R14
template <int KT, int BS>
__device__ __forceinline__ void gemm_f16(const uint4* __restrict__ Av,
                                         const uint2* __restrict__ Bv,
                                         float acc[2][4][4],
                                         int G0, int colBase, int g, int tq, int lane) {
#pragma unroll
    for (int kt = 0; kt < KT; kt++) {
        uint4 v0 = Av[(G0 * KT + kt) * 32 + lane];
        uint4 v1 = Av[((G0 + 1) * KT + kt) * 32 + lane];
#pragma unroll
        for (int n = 0; n < 4; n++) {
            uint2 b = Bv[(colBase + 8 * n + g) * BS + kt * 4 + tq];
            mma_f16(acc[0][n], v0.x, v0.z, v0.y, v0.w, b.x, b.y);
            mma_f16(acc[1][n], v1.x, v1.z, v1.y, v1.w, b.x, b.y);
        }
    }
}

// bias+relu -> f16 fragment store (KT=8 layout), conflict-free STS.128
__device__ __forceinline__ void epi_f16(float acc[2][4][4], const float* __restrict__ bias,
                                        uint4* __restrict__ Hv,
                                        int G0, int colBase, int g, int tq) {
    const int ktb = colBase >> 4;
#pragma unroll
    for (int m = 0; m < 2; m++) {
#pragma unroll
        for (int j = 0; j < 2; j++) {
            const int cl = colBase + 16 * j + 2 * tq;
            const int ch = cl + 8;
            const float bl0 = bias[cl], bl1 = bias[cl + 1];
            const float bh0 = bias[ch], bh1 = bias[ch + 1];
            uint4 v;
            v.x = h2pack(fmaxf(acc[m][2*j][0]   + bl0, 0.f), fmaxf(acc[m][2*j][1]   + bl1, 0.f));
            v.y = h2pack(fmaxf(acc[m][2*j+1][0] + bh0, 0.f), fmaxf(acc[m][2*j+1][1] + bh1, 0.f));
            v.z = h2pack(fmaxf(acc[m][2*j][2]   + bl0, 0.f), fmaxf(acc[m][2*j][3]   + bl1, 0.f));
            v.w = h2pack(fmaxf(acc[m][2*j+1][2] + bh0, 0.f), fmaxf(acc[m][2*j+1][3] + bh1, 0.f));
            Hv[((G0 + m) * 8 + ktb + j) * 32 + 4 * g + tq] = v;
        }
    }
}

// ---------------- kernel ----------------
__global__ void __launch_bounds__(NTHREADS, 1)
nca_kernel(const float* __restrict__ x,  const float* __restrict__ fm,
           const float* __restrict__ w1, const float* __restrict__ b1,
           const float* __restrict__ w2, const float* __restrict__ b2,
           const float* __restrict__ w3, const float* __restrict__ b3,
           float* __restrict__ out) {
    extern __shared__ float sm[];
    char* smb = reinterpret_cast<char*>(sm);
    const uint2* W1v = reinterpret_cast<const uint2*>(&sm[OFF_W1V]);
    const uint2* W2v = reinterpret_cast<const uint2*>(&sm[OFF_W2V]);
    const uint2* W3v = reinterpret_cast<const uint2*>(&sm[OFF_W3V]);

    const int tid  = threadIdx.x;
    const int lane = tid & 31;
    const int wid  = tid >> 5;
    const int g    = lane >> 2;
    const int tq   = lane & 3;
    const int half = wid >> 3;               // pipeline group 0/1
    const int gtid = tid & 255;
    const int gwid = wid & 7;
    const int gbar_id = 1 + half;
    // group GEMM tiling: 4 warps over M, 2 over N (x2 nb passes)
    const int rowBase = (gwid & 3) * 32;
    const int G0      = rowBase >> 4;
    const int Wn      = gwid >> 2;           // N-warp 0/1
    const int G3      = gwid;                // L3: 8 warps over M

    // ---- per-group shared regions ----
    float* gsm   = sm + OFF_G + half * GSTRIDE;
    uint4* Hv4   = reinterpret_cast<uint4*>(gsm + G_HV);
    char*  hvb   = reinterpret_cast<char*>(gsm + G_HV);
    float* xs    = gsm + G_XS;
    short* idx16 = reinterpret_cast<short*>(gsm + G_IDX);
    int*   cnt   = reinterpret_cast<int*>(gsm + G_CNT);
    int*   nlp   = reinterpret_cast<int*>(gsm + G_NL);

    // ---- stage shared weights (full CTA, once) ----
    for (int i = tid; i < 128 * 12; i += NTHREADS) {           // W1: 3kt x 4tq
        const int n = i / 12, j = i - n * 12, kt = j >> 2, tq2 = j & 3;
        const int k = 16 * kt + 2 * tq2;
        unsigned lo = h2pack(w1[k * EMB + n],       w1[(k + 1) * EMB + n]);
        unsigned hi = h2pack(w1[(k + 8) * EMB + n], w1[(k + 9) * EMB + n]);
        *(uint2*)&sm[OFF_W1V + 2 * (n * S1H + kt * 4 + tq2)] = make_uint2(lo, hi);
    }
    for (int i = tid; i < 128 * 32; i += NTHREADS) {           // W2: 8kt x 4tq
        const int n = i >> 5, j = i & 31, kt = j >> 2, tq2 = j & 3;
        const int k = 16 * kt + 2 * tq2;
        unsigned lo = h2pack(w2[k * EMB + n],       w2[(k + 1) * EMB + n]);
        unsigned hi = h2pack(w2[(k + 8) * EMB + n], w2[(k + 9) * EMB + n]);
        *(uint2*)&sm[OFF_W2V + 2 * (n * S2H + kt * 4 + tq2)] = make_uint2(lo, hi);
    }
    for (int i = tid; i < 16 * 32; i += NTHREADS) {            // W3
        const int n = i >> 5, j = i & 31, kt = j >> 2, tq2 = j & 3;
        const int k = 16 * kt + 2 * tq2;
        unsigned lo = h2pack(w3[k * CHN + n],       w3[(k + 1) * CHN + n]);
        unsigned hi = h2pack(w3[(k + 8) * CHN + n], w3[(k + 9) * CHN + n]);
        *(uint2*)&sm[OFF_W3V + 2 * (n * S2H + kt * 4 + tq2)] = make_uint2(lo, hi);
    }
    for (int i = tid; i < EMB; i += NTHREADS) {
        sm[OFF_B1 + i] = b1[i];
        sm[OFF_B2 + i] = b2[i];
    }
    if (tid < CHN) sm[OFF_B3 + tid] = b3[tid];
    // zero XS pads for BOTH groups: left (+0..+3) and right (+260..+263) of 48 rows
    for (int i = tid; i < 2 * 48 * 8; i += NTHREADS) {
        const int gi = i / (48 * 8), r2 = i - gi * 48 * 8;
        const int rr = r2 >> 3, j = r2 & 7;
        sm[OFF_G + gi * GSTRIDE + G_XS + rr * XS_ROW + (j < 4 ? j : 256 + j)] = 0.f;
    }
    __syncthreads();   // LAST full-CTA barrier; groups are independent below

    // ---- strip of contiguous pools for this group ----
    const int nstrip = 2 * gridDim.x;
    const int per = (NPOOL + nstrip - 1) / nstrip;
    const int gi  = 2 * blockIdx.x + half;
    const int t0  = gi * per;
    const int t1  = min(t0 + per, NPOOL);

    for (int t = t0; t < t1; t++) {
        const int b = t >> 8;
        const int y = t & 255;

        // ---- staging: full reload at strip/image start, else prefetch pending ----
        if (t == t0 || y == 0) {
            for (int j = y - 1; j <= y + 1; j++) {
                const int slot = ((j % 3) + 3) % 3;
                if (j < 0 || j >= HGT) {
                    for (int i = gtid; i < CHN * 256; i += 256)
                        xs[((i >> 8) * 3 + slot) * XS_ROW + 4 + (i & 255)] = 0.f;
                } else {
                    for (int i = gtid; i < CHN * 64; i += 256) {
                        const int c = i >> 6, q = i & 63;
                        cp16(&xs[(c * 3 + slot) * XS_ROW + 4 + 4 * q],
                             &x[((b * CHN + c) * HGT + j) * WID + 4 * q]);
                    }
                }
            }
            asm volatile("cp.async.commit_group;\n");
        }
        asm volatile("cp.async.wait_group 0;\n" ::: "memory");
        GBAR();

        const int st = (y + 2) % 3;   // slot of row y-1
        const int sM = y % 3;
        const int sb = (y + 1) % 3;

        // ---- sel + ballot compaction (one pixel per thread) ----
        int live;
        unsigned bal;
        {
            const int p = gtid;
            const float* at = &xs[(3 * 3 + st) * XS_ROW];
            const float* am = &xs[(3 * 3 + sM) * XS_ROW];
            const float* ab = &xs[(3 * 3 + sb) * XS_ROW];
            float m = at[p + 3];
            m = fmaxf(m, at[p + 4]); m = fmaxf(m, at[p + 5]);
            m = fmaxf(m, am[p + 3]); m = fmaxf(m, am[p + 4]); m = fmaxf(m, am[p + 5]);
            m = fmaxf(m, ab[p + 3]); m = fmaxf(m, ab[p + 4]); m = fmaxf(m, ab[p + 5]);
            float fire = fm[(b * HGT + y) * WID + p];
            live = (m > 0.1f && fire != 0.f) ? 1 : 0;
            bal = __ballot_sync(0xffffffffu, live);
            if (lane == 0) cnt[gwid] = __popc(bal);
        }
        // zero entire output row (live pixels overwritten later)
        for (int i = gtid; i < 1024; i += 256) {
            const int c = i >> 6, q = i & 63;
            *(float4*)&out[((b * CHN + c) * HGT + y) * WID + 4 * q] =
                make_float4(0.f, 0.f, 0.f, 0.f);
        }
        GBAR();
        if (gtid == 0) {
            int s = 0;
#pragma unroll
            for (int w_ = 0; w_ < 8; w_++) {
                int c = cnt[w_];
                cnt[w_] = s;
                s += c;
            }
            *nlp = s;
        }
        GBAR();
        if (live)
            idx16[cnt[gwid] + __popc(bal & ((1u << lane) - 1))] = (short)gtid;
        GBAR();
        const int NL = *nlp;
        const bool doPrefetch = (t + 1 < t1) && (y < 255);
        bool prefetched = false;

        #define ISSUE_PREFETCH() do {                                                    \
            const int j = y + 2, slot = j % 3;                                           \
            if (j < HGT) {                                                               \
                for (int i = gtid; i < CHN * 64; i += 256) {                             \
                    const int c = i >> 6, q = i & 63;                                    \
                    cp16(&xs[(c * 3 + slot) * XS_ROW + 4 + 4 * q],                       \
                         &x[((b * CHN + c) * HGT + j) * WID + 4 * q]);                   \
                }                                                                        \
                asm volatile("cp.async.commit_group;\n");                                \
            } else {                                                                     \
                for (int i = gtid; i < CHN * 256; i += 256)                              \
                    xs[((i >> 8) * 3 + slot) * XS_ROW + 4 + (i & 255)] = 0.f;            \
            }                                                                            \
        } while (0)

        if (NL == 0) {
            if (doPrefetch) ISSUE_PREFETCH();
            GBAR();
            continue;
        }

        // ---- compacted GEMM chunks of up to 128 rows ----
        for (int base = 0; base < NL; base += 128) {
            const int rows = min(128, NL - base);

            // features -> F fragment (KT=3 layout in Hv region), half2-packed
            for (int i = gtid; i < rows * 8; i += 256) {
                const int r = i >> 3, cp = i & 7;
                const int p = idx16[base + r];
                float xv[2], gx[2], gy[2];
#pragma unroll
                for (int h = 0; h < 2; h++) {
                    const int c = 2 * cp + h;
                    const float* xt = &xs[(c * 3 + st) * XS_ROW];
                    const float* xm = &xs[(c * 3 + sM) * XS_ROW];
                    const float* xb = &xs[(c * 3 + sb) * XS_ROW];
                    float x00 = xt[p + 3], x01 = xt[p + 4], x02 = xt[p + 5];
                    float x10 = xm[p + 3], x11 = xm[p + 4], x12 = xm[p + 5];
                    float x20 = xb[p + 3], x21 = xb[p + 4], x22 = xb[p + 5];
                    xv[h] = x11;
                    gx[h] = (x02 - x00) + 2.f * (x12 - x10) + (x22 - x20);
                    gy[h] = (x20 - x00) + 2.f * (x21 - x01) + (x22 - x02);
                }
                const int G = r >> 4, rr = r & 15, gg = rr & 7;
                const unsigned lanep = 4 * gg + (cp & 3);
                const unsigned sub = ((rr >> 3) << 3) + ((cp >> 2) << 2);
                const unsigned eb = ((G * 3) * 32 + lanep) * 16 + sub;
                *(unsigned*)(hvb + eb)           = h2pack(xv[0], xv[1]);   // kt 0 (x)
                *(unsigned*)(hvb + eb + 32 * 16) = h2pack(gx[0], gx[1]);   // kt 1 (gx)
                *(unsigned*)(hvb + eb + 64 * 16) = h2pack(gy[0], gy[1]);   // kt 2 (gy)
            }
            GBAR();

            if (doPrefetch && !prefetched && base + 128 >= NL) {
                ISSUE_PREFETCH();
                prefetched = true;
            }

            const bool act12 = (rowBase < rows);

            // ---- layer 1: F(KT=3) @ W1 -> H(KT=8, in place); 2 col passes ----
            {
                float acc[2][2][4][4];
#pragma unroll
                for (int nb = 0; nb < 2; nb++)
#pragma unroll
                    for (int m = 0; m < 2; m++)
#pragma unroll
                        for (int n = 0; n < 4; n++)
#pragma unroll
                            for (int j = 0; j < 4; j++) acc[nb][m][n][j] = 0.f;
                if (act12) {
                    gemm_f16<3, S1H>(Hv4, W1v, acc[0], G0, Wn * 32,      g, tq, lane);
                    gemm_f16<3, S1H>(Hv4, W1v, acc[1], G0, Wn * 32 + 64, g, tq, lane);
                }
                GBAR();   // all F reads done before overwrite
                if (act12) {
                    epi_f16(acc[0], &sm[OFF_B1], Hv4, G0, Wn * 32,      g, tq);
                    epi_f16(acc[1], &sm[OFF_B1], Hv4, G0, Wn * 32 + 64, g, tq);
                }
            }
            GBAR();

            // ---- layer 2: H @ W2 -> H (in place); 2 col passes ----
            {
                float acc[2][4][4];
#pragma unroll
                for (int m = 0; m < 2; m++)
#pragma unroll
                    for (int n = 0; n < 4; n++)
#pragma unroll
                        for (int j = 0; j < 4; j++) acc[m][n][j] = 0.f;
                float acc2[2][4][4];
#pragma unroll
                for (int m = 0; m < 2; m++)
#pragma unroll
                    for (int n = 0; n < 4; n++)
#pragma unroll
                        for (int j = 0; j < 4; j++) acc2[m][n][j] = 0.f;
                if (act12) {
                    gemm_f16<8, S2H>(Hv4, W2v, acc,  G0, Wn * 32,      g, tq, lane);
                    gemm_f16<8, S2H>(Hv4, W2v, acc2, G0, Wn * 32 + 64, g, tq, lane);
                }
                GBAR();   // all H reads done before overwrite
                if (act12) {
                    epi_f16(acc,  &sm[OFF_B2], Hv4, G0, Wn * 32,      g, tq);
                    epi_f16(acc2, &sm[OFF_B2], Hv4, G0, Wn * 32 + 64, g, tq);
                }
            }
            GBAR();

            // ---- layer 3: H @ W3[->16] -> scatter (8 warps over M, full 16 cols) ----
            if (G3 * 16 < rows) {
                float acc0[4] = {0.f, 0.f, 0.f, 0.f};
                float acc1[4] = {0.f, 0.f, 0.f, 0.f};
#pragma unroll
                for (int kt = 0; kt < 8; kt++) {
                    uint4 v = Hv4[(G3 * 8 + kt) * 32 + lane];
                    uint2 ba = W3v[g * S2H + kt * 4 + tq];
                    uint2 bb = W3v[(8 + g) * S2H + kt * 4 + tq];
                    mma_f16(acc0, v.x, v.z, v.y, v.w, ba.x, ba.y);
                    mma_f16(acc1, v.x, v.z, v.y, v.w, bb.x, bb.y);
                }
                const int c0 = 2 * tq;
                const int i0 = G3 * 16 + g;
                const int i1 = i0 + 8;
                const float b0a = sm[OFF_B3 + c0],     b1a = sm[OFF_B3 + c0 + 1];
                const float b0b = sm[OFF_B3 + 8 + c0], b1b = sm[OFF_B3 + 8 + c0 + 1];
                if (i0 < rows) {
                    const int p = idx16[base + i0];
                    out[((b * CHN + c0)         * HGT + y) * WID + p] = acc0[0] + b0a;
                    out[((b * CHN + c0 + 1)     * HGT + y) * WID + p] = acc0[1] + b1a;
                    out[((b * CHN + 8 + c0)     * HGT + y) * WID + p] = acc1[0] + b0b;
                    out[((b * CHN + 8 + c0 + 1) * HGT + y) * WID + p] = acc1[1] + b1b;
                }
                if (i1 < rows) {
                    const int p = idx16[base + i1];
                    out[((b * CHN + c0)         * HGT + y) * WID + p] = acc0[2] + b0a;
                    out[((b * CHN + c0 + 1)     * HGT + y) * WID + p] = acc0[3] + b1a;
                    out[((b * CHN + 8 + c0)     * HGT + y) * WID + p] = acc1[2] + b0b;
                    out[((b * CHN + 8 + c0 + 1) * HGT + y) * WID + p] = acc1[3] + b1b;
                }
            }
            GBAR();   // H/F reuse next chunk
        }
        #undef ISSUE_PREFETCH
    }
}

// ---------------- launch ----------------
extern "C" void kernel_launch(void* const* d_in, const int* in_sizes, int n_in,
                              void* d_out, int out_size) {
    const float* x  = (const float*)d_in[0];
    const float* fm = (const float*)d_in[1];
    const float* w1 = (const float*)d_in[2];
    const float* b1 = (const float*)d_in[3];
    const float* w2 = (const float*)d_in[4];
    const float* b2 = (const float*)d_in[5];
    const float* w3 = (const float*)d_in[6];
    const float* b3 = (const float*)d_in[7];
    float* out = (float*)d_out;

    (void)in_sizes; (void)n_in; (void)out_size;

    int dev = 0;
    cudaGetDevice(&dev);
    int sms = 148;
    cudaDeviceGetAttribute(&sms, cudaDevAttrMultiProcessorCount, dev);

    cudaFuncSetAttribute(nca_kernel, cudaFuncAttributeMaxDynamicSharedMemorySize, SMEM_BYTES);
    nca_kernel<<<sms, NTHREADS, SMEM_BYTES>>>(x, fm, w1, b1, w2, b2, w3, b3, out);
}

// round 17
// speedup vs baseline: 5.8290x; 1.5873x over previous
#include <cuda_runtime.h>
#include <cuda_fp16.h>

// ---------------- problem constants ----------------
#define CHN   16
#define EMB   128
#define HGT   256
#define WID   256
#define BATCH 16
#define POOLW 256
#define NPOOL (BATCH * HGT)   // 4096
#define NTHREADS 512

// ---------------- layouts ----------------
// Weights: uint2 per (n, kt16, tq) = {h2(W[k][n],W[k+1][n]), h2(W[k+8][n],W[k+9][n])},
// k = 16*kt + 2*tq. Row stride (uint2 units) ≡ 4 or 12 (mod 16) -> conflict-free LDS.64.
#define S1H 12                // W1: 3 kt-steps (K=48)
#define S2H 36                // W2/W3: 8 kt-steps (K=128)

#define OFF_W1V 0                         // 2*128*12 = 3072 floats
#define OFF_W2V 3072                      // 2*128*36 = 9216
#define OFF_W3V 12288                     // 2*16*36  = 1152
#define OFF_B1  13440
#define OFF_B2  13568
#define OFF_B3  13696
#define OFF_G   13712                     // two per-group regions follow
// per-group region: XS[16 ch][stride 1060]{4 slots x 264}, idx, cnt, nl
// channel stride 1060 ≡ 4 (mod 32): feature stencil banks spread {0,8,16,24} over tq
#define XS_ROW  264
#define XS_CS   1060                      // channel stride (4*264 + 4 pad)
#define G_XS    0                         // 16*1060 = 16960 floats
#define G_IDX   16960                     // 256 shorts = 128 floats
#define G_CNT   17088                     // 8 ints
#define G_NL    17096
#define GSTRIDE 17104
#define SMEM_FLOATS (OFF_G + 2 * GSTRIDE) // 47920
#define SMEM_BYTES  (SMEM_FLOATS * 4)     // 191,680 B

// ---------------- helpers ----------------
__device__ __forceinline__ unsigned h2pack(float lo, float hi) {
    unsigned r;
    asm("cvt.rn.f16x2.f32 %0, %1, %2;" : "=r"(r) : "f"(hi), "f"(lo));
    return r;
}

__device__ __forceinline__ void cp16(float* dst, const float* src) {
    unsigned d = (unsigned)__cvta_generic_to_shared(dst);
    asm volatile("cp.async.cg.shared.global [%0], [%1], 16;\n" :: "r"(d), "l"(src));
}

__device__ __forceinline__ void mma4(float* d, const unsigned a[4],
                                     unsigned b0, unsigned b1) {
    asm volatile(
        "mma.sync.aligned.m16n8k16.row.col.f32.f16.f16.f32 "
        "{%0,%1,%2,%3}, {%4,%5,%6,%7}, {%8,%9}, {%0,%1,%2,%3};\n"
        : "+f"(d[0]), "+f"(d[1]), "+f"(d[2]), "+f"(d[3])
        : "r"(a[0]), "r"(a[1]), "r"(a[2]), "r"(a[3]), "r"(b0), "r"(b1));
}

#define GBAR() asm volatile("bar.sync %0, 256;" :: "r"(gbar_id) : "memory")
#define RELU(v) fmaxf((v), 0.f)

// ---------------- kernel ----------------
__global__ void __launch_bounds__(NTHREADS, 1)
nca_kernel(const float* __restrict__ x,  const float* __restrict__ fm,
           const float* __restrict__ w1, const float* __restrict__ b1,
           const float* __restrict__ w2, const float* __restrict__ b2,
           const float* __restrict__ w3, const float* __restrict__ b3,
           float* __restrict__ out) {
    extern __shared__ float sm[];
    const uint2* W1v = reinterpret_cast<const uint2*>(&sm[OFF_W1V]);
    const uint2* W2v = reinterpret_cast<const uint2*>(&sm[OFF_W2V]);
    const uint2* W3v = reinterpret_cast<const uint2*>(&sm[OFF_W3V]);

    const int tid  = threadIdx.x;
    const int lane = tid & 31;
    const int wid  = tid >> 5;
    const int g    = lane >> 2;
    const int tq   = lane & 3;
    const int half = wid >> 3;               // pipeline group 0/1
    const int gtid = tid & 255;
    const int gwid = wid & 7;
    const int gbar_id = 1 + half;
    const int G3   = gwid;                   // exclusive 16-row band per warp

    // ---- per-group shared regions ----
    float* gsm   = sm + OFF_G + half * GSTRIDE;
    float* xs    = gsm + G_XS;
    short* idx16 = reinterpret_cast<short*>(gsm + G_IDX);
    int*   cnt   = reinterpret_cast<int*>(gsm + G_CNT);
    int*   nlp   = reinterpret_cast<int*>(gsm + G_NL);

    // ---- stage shared weights (full CTA, once) ----
    for (int i = tid; i < 128 * 12; i += NTHREADS) {           // W1: 3kt x 4tq
        const int n = i / 12, j = i - n * 12, kt = j >> 2, tq2 = j & 3;
        const int k = 16 * kt + 2 * tq2;
        unsigned lo = h2pack(w1[k * EMB + n],       w1[(k + 1) * EMB + n]);
        unsigned hi = h2pack(w1[(k + 8) * EMB + n], w1[(k + 9) * EMB + n]);
        *(uint2*)&sm[OFF_W1V + 2 * (n * S1H + kt * 4 + tq2)] = make_uint2(lo, hi);
    }
    for (int i = tid; i < 128 * 32; i += NTHREADS) {           // W2: 8kt x 4tq
        const int n = i >> 5, j = i & 31, kt = j >> 2, tq2 = j & 3;
        const int k = 16 * kt + 2 * tq2;
        unsigned lo = h2pack(w2[k * EMB + n],       w2[(k + 1) * EMB + n]);
        unsigned hi = h2pack(w2[(k + 8) * EMB + n], w2[(k + 9) * EMB + n]);
        *(uint2*)&sm[OFF_W2V + 2 * (n * S2H + kt * 4 + tq2)] = make_uint2(lo, hi);
    }
    for (int i = tid; i < 16 * 32; i += NTHREADS) {            // W3
        const int n = i >> 5, j = i & 31, kt = j >> 2, tq2 = j & 3;
        const int k = 16 * kt + 2 * tq2;
        unsigned lo = h2pack(w3[k * CHN + n],       w3[(k + 1) * CHN + n]);
        unsigned hi = h2pack(w3[(k + 8) * CHN + n], w3[(k + 9) * CHN + n]);
        *(uint2*)&sm[OFF_W3V + 2 * (n * S2H + kt * 4 + tq2)] = make_uint2(lo, hi);
    }
    for (int i = tid; i < EMB; i += NTHREADS) {
        sm[OFF_B1 + i] = b1[i];
        sm[OFF_B2 + i] = b2[i];
    }
    if (tid < CHN) sm[OFF_B3 + tid] = b3[tid];
    // zero XS pads: both groups, 16 ch x 4 slots, left (+0..3) and right (+260..263)
    for (int i = tid; i < 2 * 64 * 8; i += NTHREADS) {
        const int gi = i >> 9, r2 = i & 511;
        const int c = r2 >> 5, slot = (r2 >> 3) & 3, j = r2 & 7;
        sm[OFF_G + gi * GSTRIDE + G_XS + c * XS_CS + slot * XS_ROW +
           (j < 4 ? j : 256 + j)] = 0.f;
    }
    __syncthreads();   // LAST full-CTA barrier

    // ---- strip of contiguous pools for this group ----
    const int nstrip = 2 * gridDim.x;
    const int per = (NPOOL + nstrip - 1) / nstrip;
    const int gi  = 2 * blockIdx.x + half;
    const int t0  = gi * per;
    const int t1  = min(t0 + per, NPOOL);

    for (int t = t0; t < t1; t++) {
        const int b = t >> 8;
        const int y = t & 255;

        // ---- staging: full reload at strip/image start, else prefetch pending ----
        if (t == t0 || y == 0) {
            for (int j = y - 1; j <= y + 1; j++) {
                const int slot = ((j % 4) + 4) % 4;
                if (j < 0 || j >= HGT) {
                    for (int i = gtid; i < CHN * 256; i += 256)
                        xs[(i >> 8) * XS_CS + slot * XS_ROW + 4 + (i & 255)] = 0.f;
                } else {
                    for (int i = gtid; i < CHN * 64; i += 256) {
                        const int c = i >> 6, q = i & 63;
                        cp16(&xs[c * XS_CS + slot * XS_ROW + 4 + 4 * q],
                             &x[((b * CHN + c) * HGT + j) * WID + 4 * q]);
                    }
                }
            }
            asm volatile("cp.async.commit_group;\n");
        }
        asm volatile("cp.async.wait_group 0;\n" ::: "memory");
        GBAR();

        const int st = (y + 3) % 4;   // slot of row y-1
        const int sM = y % 4;
        const int sb = (y + 1) % 4;

        // ---- sel + ballot compaction ----
        int live;
        unsigned bal;
        {
            const int p = gtid;
            const float* at = &xs[3 * XS_CS + st * XS_ROW];
            const float* am = &xs[3 * XS_CS + sM * XS_ROW];
            const float* ab = &xs[3 * XS_CS + sb * XS_ROW];
            float m = at[p + 3];
            m = fmaxf(m, at[p + 4]); m = fmaxf(m, at[p + 5]);
            m = fmaxf(m, am[p + 3]); m = fmaxf(m, am[p + 4]); m = fmaxf(m, am[p + 5]);
            m = fmaxf(m, ab[p + 3]); m = fmaxf(m, ab[p + 4]); m = fmaxf(m, ab[p + 5]);
            float fire = fm[(b * HGT + y) * WID + p];
            live = (m > 0.1f && fire != 0.f) ? 1 : 0;
            bal = __ballot_sync(0xffffffffu, live);
            if (lane == 0) cnt[gwid] = __popc(bal);
        }
        // zero entire output row (live pixels overwritten later)
        for (int i = gtid; i < 1024; i += 256) {
            const int c = i >> 6, q = i & 63;
            *(float4*)&out[((b * CHN + c) * HGT + y) * WID + 4 * q] =
                make_float4(0.f, 0.f, 0.f, 0.f);
        }
        GBAR();
        if (gtid == 0) {
            int s = 0;
#pragma unroll
            for (int w_ = 0; w_ < 8; w_++) {
                int c = cnt[w_];
                cnt[w_] = s;
                s += c;
            }
            *nlp = s;
        }
        GBAR();
        if (live)
            idx16[cnt[gwid] + __popc(bal & ((1u << lane) - 1))] = (short)gtid;
        GBAR();
        const int NL = *nlp;

        // ---- prefetch next pool's row y+2 into slot (y+2)%4 (not read this pool) ----
        if ((t + 1 < t1) && (y < 255)) {
            const int j = y + 2, slot = (y + 2) % 4;
            if (j < HGT) {
                for (int i = gtid; i < CHN * 64; i += 256) {
                    const int c = i >> 6, q = i & 63;
                    cp16(&xs[c * XS_CS + slot * XS_ROW + 4 + 4 * q],
                         &x[((b * CHN + c) * HGT + j) * WID + 4 * q]);
                }
                asm volatile("cp.async.commit_group;\n");
            } else {
                for (int i = gtid; i < CHN * 256; i += 256)
                    xs[(i >> 8) * XS_CS + slot * XS_ROW + 4 + (i & 255)] = 0.f;
            }
        }

        // ---- chunks of up to 128 rows: per-warp fused register-resident MLP ----
        for (int base = 0; base < NL; base += 128) {
            const int rows = min(128, NL - base);
            if (G3 * 16 >= rows) continue;

            const int rg = G3 * 16 + g;
            const int p0 = (rg     < rows) ? (int)idx16[base + rg]     : -1;
            const int p1 = (rg + 8 < rows) ? (int)idx16[base + rg + 8] : -1;

            // ---- features -> A-fragments aF[3][4] (kt0=x, kt1=gx, kt2=gy) ----
            unsigned aF[3][4];
            {
                float X[2][4], GX[2][4], GY[2][4];
#pragma unroll
                for (int h = 0; h < 2; h++) {
                    const int p = h ? p1 : p0;
#pragma unroll
                    for (int j = 0; j < 4; j++) {
                        if (p >= 0) {
                            const int c = 2 * tq + (j & 1) + ((j >> 1) << 3);
                            const float* xt = &xs[c * XS_CS + st * XS_ROW];
                            const float* xm = &xs[c * XS_CS + sM * XS_ROW];
                            const float* xb = &xs[c * XS_CS + sb * XS_ROW];
                            float x00 = xt[p+3], x01 = xt[p+4], x02 = xt[p+5];
                            float x10 = xm[p+3], x11 = xm[p+4], x12 = xm[p+5];
                            float x20 = xb[p+3], x21 = xb[p+4], x22 = xb[p+5];
                            X [h][j] = x11;
                            GX[h][j] = (x02 - x00) + 2.f * (x12 - x10) + (x22 - x20);
                            GY[h][j] = (x20 - x00) + 2.f * (x21 - x01) + (x22 - x02);
                        } else {
                            X[h][j] = 0.f; GX[h][j] = 0.f; GY[h][j] = 0.f;
                        }
                    }
                }
                aF[0][0] = h2pack(X [0][0], X [0][1]); aF[0][1] = h2pack(X [1][0], X [1][1]);
                aF[0][2] = h2pack(X [0][2], X [0][3]); aF[0][3] = h2pack(X [1][2], X [1][3]);
                aF[1][0] = h2pack(GX[0][0], GX[0][1]); aF[1][1] = h2pack(GX[1][0], GX[1][1]);
                aF[1][2] = h2pack(GX[0][2], GX[0][3]); aF[1][3] = h2pack(GX[1][2], GX[1][3]);
                aF[2][0] = h2pack(GY[0][0], GY[0][1]); aF[2][1] = h2pack(GY[1][0], GY[1][1]);
                aF[2][2] = h2pack(GY[0][2], GY[0][3]); aF[2][3] = h2pack(GY[1][2], GY[1][3]);
            }

            float acc[8][4];
            unsigned aH[8][4];

            // ---- layer 1: two 64-col halves; C-frag -> A-frag repack in regs ----
#pragma unroll
            for (int hf = 0; hf < 2; hf++) {
#pragma unroll
                for (int nt = 0; nt < 8; nt++)
#pragma unroll
                    for (int j = 0; j < 4; j++) acc[nt][j] = 0.f;
#pragma unroll
                for (int kt = 0; kt < 3; kt++)
#pragma unroll
                    for (int nt = 0; nt < 8; nt++) {
                        uint2 bw = W1v[(64 * hf + 8 * nt + g) * S1H + kt * 4 + tq];
                        mma4(acc[nt], aF[kt], bw.x, bw.y);
                    }
#pragma unroll
                for (int tt = 0; tt < 4; tt++) {
                    const int cb = 64 * hf + 16 * tt;
                    float2 bl = *(const float2*)&sm[OFF_B1 + cb + 2 * tq];
                    float2 bh = *(const float2*)&sm[OFF_B1 + cb + 8 + 2 * tq];
                    aH[4*hf+tt][0] = h2pack(RELU(acc[2*tt][0]   + bl.x), RELU(acc[2*tt][1]   + bl.y));
                    aH[4*hf+tt][1] = h2pack(RELU(acc[2*tt][2]   + bl.x), RELU(acc[2*tt][3]   + bl.y));
                    aH[4*hf+tt][2] = h2pack(RELU(acc[2*tt+1][0] + bh.x), RELU(acc[2*tt+1][1] + bh.y));
                    aH[4*hf+tt][3] = h2pack(RELU(acc[2*tt+1][2] + bh.x), RELU(acc[2*tt+1][3] + bh.y));
                }
            }

            // ---- layer 2: same pattern, aH -> aH2 ----
            unsigned aH2[8][4];
#pragma unroll
            for (int hf = 0; hf < 2; hf++) {
#pragma unroll
                for (int nt = 0; nt < 8; nt++)
#pragma unroll
                    for (int j = 0; j < 4; j++) acc[nt][j] = 0.f;
#pragma unroll
                for (int kt = 0; kt < 8; kt++)
#pragma unroll
                    for (int nt = 0; nt < 8; nt++) {
                        uint2 bw = W2v[(64 * hf + 8 * nt + g) * S2H + kt * 4 + tq];
                        mma4(acc[nt], aH[kt], bw.x, bw.y);
                    }
#pragma unroll
                for (int tt = 0; tt < 4; tt++) {
                    const int cb = 64 * hf + 16 * tt;
                    float2 bl = *(const float2*)&sm[OFF_B2 + cb + 2 * tq];
                    float2 bh = *(const float2*)&sm[OFF_B2 + cb + 8 + 2 * tq];
                    aH2[4*hf+tt][0] = h2pack(RELU(acc[2*tt][0]   + bl.x), RELU(acc[2*tt][1]   + bl.y));
                    aH2[4*hf+tt][1] = h2pack(RELU(acc[2*tt][2]   + bl.x), RELU(acc[2*tt][3]   + bl.y));
                    aH2[4*hf+tt][2] = h2pack(RELU(acc[2*tt+1][0] + bh.x), RELU(acc[2*tt+1][1] + bh.y));
                    aH2[4*hf+tt][3] = h2pack(RELU(acc[2*tt+1][2] + bh.x), RELU(acc[2*tt+1][3] + bh.y));
                }
            }

            // ---- layer 3: 16 cols, scatter ----
            float a3[2][4];
#pragma unroll
            for (int nt = 0; nt < 2; nt++)
#pragma unroll
                for (int j = 0; j < 4; j++) a3[nt][j] = 0.f;
#pragma unroll
            for (int kt = 0; kt < 8; kt++)
#pragma unroll
                for (int nt = 0; nt < 2; nt++) {
                    uint2 bw = W3v[(8 * nt + g) * S2H + kt * 4 + tq];
                    mma4(a3[nt], aH2[kt], bw.x, bw.y);
                }
#pragma unroll
            for (int nt = 0; nt < 2; nt++) {
                const int c = 8 * nt + 2 * tq;
                const float b3a = sm[OFF_B3 + c], b3b = sm[OFF_B3 + c + 1];
                if (p0 >= 0) {
                    out[((b * CHN + c)     * HGT + y) * WID + p0] = a3[nt][0] + b3a;
                    out[((b * CHN + c + 1) * HGT + y) * WID + p0] = a3[nt][1] + b3b;
                }
                if (p1 >= 0) {
                    out[((b * CHN + c)     * HGT + y) * WID + p1] = a3[nt][2] + b3a;
                    out[((b * CHN + c + 1) * HGT + y) * WID + p1] = a3[nt][3] + b3b;
                }
            }
        }
        GBAR();   // protect XS (full-reload case) + idx16/cnt before next pool
    }
}

// ---------------- launch ----------------
extern "C" void kernel_launch(void* const* d_in, const int* in_sizes, int n_in,
                              void* d_out, int out_size) {
    const float* x  = (const float*)d_in[0];
    const float* fm = (const float*)d_in[1];
    const float* w1 = (const float*)d_in[2];
    const float* b1 = (const float*)d_in[3];
    const float* w2 = (const float*)d_in[4];
    const float* b2 = (const float*)d_in[5];
    const float* w3 = (const float*)d_in[6];
    const float* b3 = (const float*)d_in[7];
    float* out = (float*)d_out;

    (void)in_sizes; (void)n_in; (void)out_size;

    int dev = 0;
    cudaGetDevice(&dev);
    int sms = 148;
    cudaDeviceGetAttribute(&sms, cudaDevAttrMultiProcessorCount, dev);

    cudaFuncSetAttribute(nca_kernel, cudaFuncAttributeMaxDynamicSharedMemorySize, SMEM_BYTES);
    nca_kernel<<<sms, NTHREADS, SMEM_BYTES>>>(x, fm, w1, b1, w2, b2, w3, b3, out);
}